// round 1
// baseline (speedup 1.0000x reference)
#include <cuda_runtime.h>
#include <math.h>

// Problem constants
#define B_   2
#define S_   2048
#define HID_ 2048
#define H_   16
#define KV_  8
#define D_   128
#define MTOK (B_*S_)   // 4096 tokens

// ---------------- scratch (device globals; no allocation allowed) ----------
__device__ float g_q [MTOK * (H_*D_)];     // 4096 x 2048
__device__ float g_k [MTOK * (KV_*D_)];    // 4096 x 1024
__device__ float g_v [MTOK * (KV_*D_)];    // 4096 x 1024
__device__ float g_qr[B_*H_*S_*D_];        // [B,H,S,D]
__device__ float g_kr[B_*KV_*S_*D_];       // [B,KV,S,D]
__device__ float g_vt[B_*KV_*S_*D_];       // [B,KV,S,D]
__device__ float g_attn[MTOK * (H_*D_)];   // [B*S, H*D]

// ---------------- SGEMM NT: C[M,N] = A[M,K] * B[N,K]^T  (both row-major) ----
#define GBM 128
#define GBN 128
#define GBK 16
#define GLD 132   // padded leading dim (floats) for smem tiles

__global__ __launch_bounds__(256, 2)
void sgemm_nt(const float* __restrict__ A, const float* __restrict__ Bm,
              float* __restrict__ C, int M, int N, int K)
{
    __shared__ float As[GBK][GLD];
    __shared__ float Bs[GBK][GLD];
    const int tid = threadIdx.x;
    const int tx = tid & 15;
    const int ty = tid >> 4;
    const float* Ab = A  + (size_t)blockIdx.y * GBM * K;
    const float* Bb = Bm + (size_t)blockIdx.x * GBN * K;

    float acc[8][8];
#pragma unroll
    for (int i = 0; i < 8; i++)
#pragma unroll
        for (int j = 0; j < 8; j++) acc[i][j] = 0.f;

    for (int kt = 0; kt < K; kt += GBK) {
#pragma unroll
        for (int l = 0; l < 2; l++) {
            int id  = tid + (l << 8);      // 0..511
            int row = id >> 2;             // 0..127
            int kq  = (id & 3) << 2;       // 0,4,8,12
            float4 a4 = *(const float4*)(Ab + (size_t)row * K + kt + kq);
            As[kq + 0][row] = a4.x; As[kq + 1][row] = a4.y;
            As[kq + 2][row] = a4.z; As[kq + 3][row] = a4.w;
            float4 b4 = *(const float4*)(Bb + (size_t)row * K + kt + kq);
            Bs[kq + 0][row] = b4.x; Bs[kq + 1][row] = b4.y;
            Bs[kq + 2][row] = b4.z; Bs[kq + 3][row] = b4.w;
        }
        __syncthreads();
#pragma unroll
        for (int kk = 0; kk < GBK; kk++) {
            float4 a0 = *(const float4*)&As[kk][ty * 8];
            float4 a1 = *(const float4*)&As[kk][ty * 8 + 4];
            float4 b0 = *(const float4*)&Bs[kk][tx * 8];
            float4 b1 = *(const float4*)&Bs[kk][tx * 8 + 4];
            float ar[8] = {a0.x, a0.y, a0.z, a0.w, a1.x, a1.y, a1.z, a1.w};
            float br[8] = {b0.x, b0.y, b0.z, b0.w, b1.x, b1.y, b1.z, b1.w};
#pragma unroll
            for (int i = 0; i < 8; i++)
#pragma unroll
                for (int j = 0; j < 8; j++)
                    acc[i][j] += ar[i] * br[j];
        }
        __syncthreads();
    }
#pragma unroll
    for (int i = 0; i < 8; i++) {
        size_t r = (size_t)(blockIdx.y * GBM + ty * 8 + i) * N + blockIdx.x * GBN + tx * 8;
        *(float4*)(C + r)     = make_float4(acc[i][0], acc[i][1], acc[i][2], acc[i][3]);
        *(float4*)(C + r + 4) = make_float4(acc[i][4], acc[i][5], acc[i][6], acc[i][7]);
    }
}

// ---------------- RMSNorm + mrope + transpose -------------------------------
__device__ __forceinline__ int mrope_axis(int d) {
    // sections [21,21,22,21,21,22]; axis = chunk % 3
    return d < 21 ? 0 : d < 42 ? 1 : d < 64 ? 2 : d < 85 ? 0 : d < 106 ? 1 : 2;
}

__global__ __launch_bounds__(256)
void norm_rope_kernel(const float* __restrict__ cosb, const float* __restrict__ sinb,
                      const float* __restrict__ qw,   const float* __restrict__ kw)
{
    const int m = blockIdx.x;          // token index b*S + s
    const int b = m >> 11;
    const int s = m & (S_ - 1);
    const int warp = threadIdx.x >> 5;
    const int lane = threadIdx.x & 31;

#pragma unroll
    for (int it = 0; it < 4; it++) {
        int slot = warp + (it << 3);   // 0..31: 16 q heads, 8 k heads, 8 v heads
        const float* src; float* dst; const float* w; bool rope;
        if (slot < 16) {
            src = g_q + (size_t)m * (H_ * D_) + slot * D_;
            dst = g_qr + ((size_t)(b * H_ + slot) * S_ + s) * D_;
            w = qw; rope = true;
        } else if (slot < 24) {
            int hh = slot - 16;
            src = g_k + (size_t)m * (KV_ * D_) + hh * D_;
            dst = g_kr + ((size_t)(b * KV_ + hh) * S_ + s) * D_;
            w = kw; rope = true;
        } else {
            int hh = slot - 24;
            src = g_v + (size_t)m * (KV_ * D_) + hh * D_;
            dst = g_vt + ((size_t)(b * KV_ + hh) * S_ + s) * D_;
            w = nullptr; rope = false;
        }
        float4 x4 = *(const float4*)(src + lane * 4);
        if (!rope) {
            *(float4*)(dst + lane * 4) = x4;
            continue;
        }
        float x[4] = {x4.x, x4.y, x4.z, x4.w};
        float ssum = x[0]*x[0] + x[1]*x[1] + x[2]*x[2] + x[3]*x[3];
#pragma unroll
        for (int o = 16; o > 0; o >>= 1)
            ssum += __shfl_xor_sync(0xffffffffu, ssum, o);
        float r = rsqrtf(ssum * (1.0f / 128.0f) + 1e-6f);
        float4 w4 = *(const float4*)(w + lane * 4);
        float xn[4];
        xn[0] = x[0] * r * w4.x; xn[1] = x[1] * r * w4.y;
        xn[2] = x[2] * r * w4.z; xn[3] = x[3] * r * w4.w;
        // rotate_half partner: lanes 0-15 hold d<64, partner at lane^16
        float oth[4];
#pragma unroll
        for (int j = 0; j < 4; j++)
            oth[j] = __shfl_xor_sync(0xffffffffu, xn[j], 16);
        float sgn = (lane < 16) ? -1.f : 1.f;
        int dbase = lane * 4;
        float out[4];
#pragma unroll
        for (int j = 0; j < 4; j++) {
            int d = dbase + j;
            int ax = mrope_axis(d);
            size_t ci = ((size_t)(ax * B_ + b) * S_ + s) * D_ + d;
            out[j] = xn[j] * cosb[ci] + sgn * oth[j] * sinb[ci];
        }
        *(float4*)(dst + lane * 4) = make_float4(out[0], out[1], out[2], out[3]);
    }
}

// ---------------- causal GQA flash attention (fp32) -------------------------
#define FQT_LD 68
#define FVS_LD 132
#define FPT_LD 68
#define FLASH_SMEM ((128*FQT_LD + 128*FQT_LD + 64*FVS_LD + 64*FPT_LD) * 4)

__global__ __launch_bounds__(256, 1)
void flash_kernel(const float* __restrict__ Q, const float* __restrict__ K,
                  const float* __restrict__ V, float* __restrict__ O)
{
    extern __shared__ float sm[];
    float* Qt = sm;                       // [128][FQT_LD] : Qt[d][row]
    float* Kt = Qt + 128 * FQT_LD;        // [128][FQT_LD] : Kt[d][col]
    float* Vs = Kt + 128 * FQT_LD;        // [64][FVS_LD]  : Vs[k][d]
    float* Pt = Vs + 64 * FVS_LD;         // [64][FPT_LD]  : Pt[k][row]

    const int qt = blockIdx.x, h = blockIdx.y, b = blockIdx.z;
    const int tid = threadIdx.x;
    const int tx = tid & 15;
    const int ty = tid >> 4;
    const int q0 = qt * 64;
    const float* Qb = Q + ((size_t)(b * H_ + h) * S_ + q0) * D_;
    const float* Kb = K + ((size_t)(b * KV_ + (h >> 1)) * S_) * D_;
    const float* Vb = V + ((size_t)(b * KV_ + (h >> 1)) * S_) * D_;

    // load Q tile transposed
#pragma unroll
    for (int it = 0; it < 8; it++) {
        int id  = tid + (it << 8);
        int row = id >> 5;
        int dq  = (id & 31) << 2;
        float4 q4 = *(const float4*)(Qb + (size_t)row * D_ + dq);
        Qt[(dq + 0) * FQT_LD + row] = q4.x;
        Qt[(dq + 1) * FQT_LD + row] = q4.y;
        Qt[(dq + 2) * FQT_LD + row] = q4.z;
        Qt[(dq + 3) * FQT_LD + row] = q4.w;
    }

    float m_i[4], l_i[4], acc[4][8];
#pragma unroll
    for (int i = 0; i < 4; i++) {
        m_i[i] = -1e30f; l_i[i] = 0.f;
#pragma unroll
        for (int j = 0; j < 8; j++) acc[i][j] = 0.f;
    }

    const float SC = 0.08838834764831845f;  // 128^-0.5
    const int ntiles = qt + 1;              // causal: only tiles up to diagonal

    for (int t = 0; t < ntiles; t++) {
        const int k0 = t * 64;
        __syncthreads();   // previous PV reads done; also makes Qt visible at t=0
#pragma unroll
        for (int it = 0; it < 8; it++) {
            int id  = tid + (it << 8);
            int row = id >> 5;
            int dq  = (id & 31) << 2;
            float4 k4 = *(const float4*)(Kb + (size_t)(k0 + row) * D_ + dq);
            Kt[(dq + 0) * FQT_LD + row] = k4.x;
            Kt[(dq + 1) * FQT_LD + row] = k4.y;
            Kt[(dq + 2) * FQT_LD + row] = k4.z;
            Kt[(dq + 3) * FQT_LD + row] = k4.w;
            float4 v4 = *(const float4*)(Vb + (size_t)(k0 + row) * D_ + dq);
            *(float4*)(Vs + row * FVS_LD + dq) = v4;
        }
        __syncthreads();

        // S = Q K^T : each thread rows ty*4+i, cols tx*4+j
        float sv[4][4];
#pragma unroll
        for (int i = 0; i < 4; i++)
#pragma unroll
            for (int j = 0; j < 4; j++) sv[i][j] = 0.f;
        for (int d = 0; d < D_; d++) {
            float4 a  = *(const float4*)&Qt[d * FQT_LD + (ty << 2)];
            float4 bb = *(const float4*)&Kt[d * FQT_LD + (tx << 2)];
            float av[4] = {a.x, a.y, a.z, a.w};
            float bv[4] = {bb.x, bb.y, bb.z, bb.w};
#pragma unroll
            for (int i = 0; i < 4; i++)
#pragma unroll
                for (int j = 0; j < 4; j++)
                    sv[i][j] += av[i] * bv[j];
        }

        // scale, causal mask, online softmax update
#pragma unroll
        for (int i = 0; i < 4; i++) {
            int qi = q0 + (ty << 2) + i;
            float rm = -1e30f;
#pragma unroll
            for (int j = 0; j < 4; j++) {
                int kj = k0 + (tx << 2) + j;
                float v = (kj <= qi) ? sv[i][j] * SC : -1e30f;
                sv[i][j] = v;
                rm = fmaxf(rm, v);
            }
#pragma unroll
            for (int o = 8; o > 0; o >>= 1)
                rm = fmaxf(rm, __shfl_xor_sync(0xffffffffu, rm, o, 16));
            float mn = fmaxf(m_i[i], rm);
            float alpha = __expf(m_i[i] - mn);
            m_i[i] = mn;
            float rs = 0.f;
#pragma unroll
            for (int j = 0; j < 4; j++) {
                float p = __expf(sv[i][j] - mn);
                sv[i][j] = p;
                rs += p;
            }
#pragma unroll
            for (int o = 8; o > 0; o >>= 1)
                rs += __shfl_xor_sync(0xffffffffu, rs, o, 16);
            l_i[i] = l_i[i] * alpha + rs;
#pragma unroll
            for (int j = 0; j < 8; j++) acc[i][j] *= alpha;
        }

        // write P transposed: Pt[col][row]
#pragma unroll
        for (int i = 0; i < 4; i++)
#pragma unroll
            for (int j = 0; j < 4; j++)
                Pt[((tx << 2) + j) * FPT_LD + (ty << 2) + i] = sv[i][j];
        __syncthreads();

        // O += P @ V : rows ty*4+i, cols tx*8+j
        for (int k = 0; k < 64; k++) {
            float4 p4 = *(const float4*)&Pt[k * FPT_LD + (ty << 2)];
            float4 v0 = *(const float4*)&Vs[k * FVS_LD + (tx << 3)];
            float4 v1 = *(const float4*)&Vs[k * FVS_LD + (tx << 3) + 4];
            float pv[4] = {p4.x, p4.y, p4.z, p4.w};
            float vv[8] = {v0.x, v0.y, v0.z, v0.w, v1.x, v1.y, v1.z, v1.w};
#pragma unroll
            for (int i = 0; i < 4; i++)
#pragma unroll
                for (int j = 0; j < 8; j++)
                    acc[i][j] += pv[i] * vv[j];
        }
    }

    // epilogue: normalize, write [B,S,H*D] flat
#pragma unroll
    for (int i = 0; i < 4; i++) {
        float inv = 1.f / l_i[i];
        size_t off = ((size_t)(b * S_ + q0 + (ty << 2) + i)) * (H_ * D_) + h * D_ + (tx << 3);
        *(float4*)(O + off)     = make_float4(acc[i][0]*inv, acc[i][1]*inv, acc[i][2]*inv, acc[i][3]*inv);
        *(float4*)(O + off + 4) = make_float4(acc[i][4]*inv, acc[i][5]*inv, acc[i][6]*inv, acc[i][7]*inv);
    }
}

// ---------------- launcher ---------------------------------------------------
extern "C" void kernel_launch(void* const* d_in, const int* in_sizes, int n_in,
                              void* d_out, int out_size)
{
    const float* hidden   = (const float*)d_in[0];
    const float* cosb     = (const float*)d_in[1];
    const float* sinb     = (const float*)d_in[2];
    const float* q_w      = (const float*)d_in[3];
    const float* k_w      = (const float*)d_in[4];
    const float* v_w      = (const float*)d_in[5];
    const float* o_w      = (const float*)d_in[6];
    const float* q_norm_w = (const float*)d_in[7];
    const float* k_norm_w = (const float*)d_in[8];
    float* out = (float*)d_out;

    float *pq, *pk, *pv, *pqr, *pkr, *pvt, *pattn;
    cudaGetSymbolAddress((void**)&pq,    g_q);
    cudaGetSymbolAddress((void**)&pk,    g_k);
    cudaGetSymbolAddress((void**)&pv,    g_v);
    cudaGetSymbolAddress((void**)&pqr,   g_qr);
    cudaGetSymbolAddress((void**)&pkr,   g_kr);
    cudaGetSymbolAddress((void**)&pvt,   g_vt);
    cudaGetSymbolAddress((void**)&pattn, g_attn);
    cudaFuncSetAttribute(flash_kernel, cudaFuncAttributeMaxDynamicSharedMemorySize, FLASH_SMEM);

    dim3 blk(256);
    // QKV projections
    sgemm_nt<<<dim3(HID_ / GBN, MTOK / GBM), blk>>>(hidden, q_w, pq, MTOK, H_ * D_, HID_);
    sgemm_nt<<<dim3((KV_ * D_) / GBN, MTOK / GBM), blk>>>(hidden, k_w, pk, MTOK, KV_ * D_, HID_);
    sgemm_nt<<<dim3((KV_ * D_) / GBN, MTOK / GBM), blk>>>(hidden, v_w, pv, MTOK, KV_ * D_, HID_);
    // RMSNorm + mrope + layout transform
    norm_rope_kernel<<<MTOK, 256>>>(cosb, sinb, q_norm_w, k_norm_w);
    // causal GQA flash attention
    flash_kernel<<<dim3(S_ / 64, H_, B_), blk, FLASH_SMEM>>>(pqr, pkr, pvt, pattn);
    // output projection -> d_out
    sgemm_nt<<<dim3(HID_ / GBN, MTOK / GBM), blk>>>(pattn, o_w, out, MTOK, HID_, HID_);
}

// round 3
// speedup vs baseline: 1.4938x; 1.4938x over previous
#include <cuda_runtime.h>
#include <cuda_bf16.h>
#include <math.h>
#include <stdint.h>

// Problem constants
#define B_   2
#define S_   2048
#define HID_ 2048
#define H_   16
#define KV_  8
#define D_   128
#define MTOK (B_*S_)   // 4096 tokens

// ---------------- scratch (device globals; no allocation allowed) ----------
__device__ float g_q [MTOK * (H_*D_)];
__device__ float g_k [MTOK * (KV_*D_)];
__device__ float g_v [MTOK * (KV_*D_)];
__device__ float g_qr[B_*H_*S_*D_];
__device__ float g_kr[B_*KV_*S_*D_];
__device__ float g_vt[B_*KV_*S_*D_];
__device__ float g_attn[MTOK * (H_*D_)];

// bf16 hi/lo split operands for tensor-core GEMMs
__device__ __nv_bfloat16 g_hid_h[MTOK*HID_],      g_hid_l[MTOK*HID_];
__device__ __nv_bfloat16 g_qw_h [H_*D_*HID_],     g_qw_l [H_*D_*HID_];
__device__ __nv_bfloat16 g_kw_h [KV_*D_*HID_],    g_kw_l [KV_*D_*HID_];
__device__ __nv_bfloat16 g_vw_h [KV_*D_*HID_],    g_vw_l [KV_*D_*HID_];
__device__ __nv_bfloat16 g_ow_h [HID_*H_*D_],     g_ow_l [HID_*H_*D_];
__device__ __nv_bfloat16 g_at_h [MTOK*H_*D_],     g_at_l [MTOK*H_*D_];

// ======================= small PTX helpers (sm_80-era, safe) ===============
__device__ __forceinline__ uint32_t smem_u32(const void* p) {
    return (uint32_t)__cvta_generic_to_shared(p);
}
__device__ __forceinline__ void cpasync16(uint32_t dst, const void* src) {
    asm volatile("cp.async.cg.shared.global [%0], [%1], 16;" :: "r"(dst), "l"(src));
}
#define CP_COMMIT() asm volatile("cp.async.commit_group;" ::: "memory")
#define CP_WAIT1()  asm volatile("cp.async.wait_group 1;" ::: "memory")

__device__ __forceinline__ void ldmx4(uint32_t* r, uint32_t addr) {
    asm volatile("ldmatrix.sync.aligned.m8n8.x4.shared.b16 {%0,%1,%2,%3}, [%4];"
                 : "=r"(r[0]), "=r"(r[1]), "=r"(r[2]), "=r"(r[3]) : "r"(addr));
}
__device__ __forceinline__ void mma16816(float* d, const uint32_t* a, const uint32_t* b) {
    asm volatile("mma.sync.aligned.m16n8k16.row.col.f32.bf16.bf16.f32 "
                 "{%0,%1,%2,%3}, {%4,%5,%6,%7}, {%8,%9}, {%0,%1,%2,%3};"
                 : "+f"(d[0]), "+f"(d[1]), "+f"(d[2]), "+f"(d[3])
                 : "r"(a[0]), "r"(a[1]), "r"(a[2]), "r"(a[3]), "r"(b[0]), "r"(b[1]));
}

// ======================= fp32 -> bf16 hi/lo split ==========================
__global__ __launch_bounds__(256)
void split_bf16_kernel(const float* __restrict__ src,
                       __nv_bfloat16* __restrict__ hi,
                       __nv_bfloat16* __restrict__ lo, int n4)
{
    int i = blockIdx.x * blockDim.x + threadIdx.x;
    if (i >= n4) return;
    float4 x = ((const float4*)src)[i];
    float xs[4] = {x.x, x.y, x.z, x.w};
    __nv_bfloat16 h[4], l[4];
#pragma unroll
    for (int j = 0; j < 4; j++) {
        h[j] = __float2bfloat16_rn(xs[j]);
        l[j] = __float2bfloat16_rn(xs[j] - __bfloat162float(h[j]));
    }
    __nv_bfloat162 h0; h0.x = h[0]; h0.y = h[1];
    __nv_bfloat162 h1; h1.x = h[2]; h1.y = h[3];
    __nv_bfloat162 l0; l0.x = l[0]; l0.y = l[1];
    __nv_bfloat162 l1; l1.x = l[2]; l1.y = l[3];
    ((__nv_bfloat162*)hi)[i*2 + 0] = h0;
    ((__nv_bfloat162*)hi)[i*2 + 1] = h1;
    ((__nv_bfloat162*)lo)[i*2 + 0] = l0;
    ((__nv_bfloat162*)lo)[i*2 + 1] = l1;
}

// ======================= mma.sync bf16x3 GEMM (NT) =========================
// C[M,N] = A[M,K]*B[N,K]^T, fp32 acc. A/B given as bf16 hi/lo pairs.
// Block tile 128x128, K-chunk 32. 3-stage cp.async pipeline.
#define LDT   40                 // padded smem row length (bf16 elems) = 80B
#define TILE_B (128*LDT*2)       // 10240 bytes per operand tile
#define STG_B  (4*TILE_B)        // 40960 bytes per stage (Ah,Al,Bh,Bl)
#define NSTG  3
#define GEMM_SMEM (NSTG*STG_B)   // 122880

__device__ __forceinline__ void load_stage(
    uint32_t sbase, int stg,
    const __nv_bfloat16* __restrict__ Ah, const __nv_bfloat16* __restrict__ Al,
    const __nv_bfloat16* __restrict__ Bh, const __nv_bfloat16* __restrict__ Bl,
    int m0, int n0, int K, int k0, int tid)
{
    uint32_t sd = sbase + stg * STG_B;
#pragma unroll
    for (int i = 0; i < 8; i++) {
        int chunk = i * 256 + tid;
        int tile  = chunk >> 9;        // 0..3 (uniform per i)
        int idx   = chunk & 511;
        int row   = idx >> 2;
        int cseg  = idx & 3;
        const __nv_bfloat16* g = (tile == 0) ? Ah : (tile == 1) ? Al : (tile == 2) ? Bh : Bl;
        int grow = ((tile < 2) ? m0 : n0) + row;
        const char* src = (const char*)(g + (size_t)grow * K + k0) + cseg * 16;
        cpasync16(sd + tile * TILE_B + row * 80 + cseg * 16, src);
    }
}

__global__ __launch_bounds__(256, 1)
void gemm_mma(const __nv_bfloat16* __restrict__ Ah, const __nv_bfloat16* __restrict__ Al,
              const __nv_bfloat16* __restrict__ Bh, const __nv_bfloat16* __restrict__ Bl,
              float* __restrict__ C, int N, int K)
{
    extern __shared__ char dsm[];
    const uint32_t sb = smem_u32(dsm);
    const int tid = threadIdx.x;
    const int w = tid >> 5;
    const int l = tid & 31;
    const int wm = (w >> 2) * 64;     // warp M offset within tile
    const int wn = (w & 3) * 32;      // warp N offset within tile
    const int m0 = blockIdx.y * 128;
    const int n0 = blockIdx.x * 128;
    const int kiters = K / 32;

    load_stage(sb, 0, Ah, Al, Bh, Bl, m0, n0, K, 0, tid);  CP_COMMIT();
    load_stage(sb, 1, Ah, Al, Bh, Bl, m0, n0, K, 32, tid); CP_COMMIT();

    float acc[16][4];
#pragma unroll
    for (int i = 0; i < 16; i++)
#pragma unroll
        for (int j = 0; j < 4; j++) acc[i][j] = 0.f;

    // ldmatrix lane addressing (element offsets within a tile)
    const int a_row = (l & 15);             // + mi*16 + wm
    const int a_kof = (l >> 4) * 8;         // 0/8
    const int b_row = (l & 7) + ((l >> 4) & 1) * 8;   // + ni2*16 + wn
    const int b_kof = ((l >> 3) & 1) * 8;

    for (int kt = 0; kt < kiters; kt++) {
        CP_WAIT1();
        __syncthreads();
        const uint32_t st = sb + (kt % 3) * STG_B;
        const uint32_t sAh = st;
        const uint32_t sAl = st + TILE_B;
        const uint32_t sBh = st + 2 * TILE_B;
        const uint32_t sBl = st + 3 * TILE_B;

#pragma unroll
        for (int ks = 0; ks < 2; ks++) {
            const int kbase = ks * 16;
            uint32_t ah[4][4], al[4][4], bh[2][4], bl[2][4];
#pragma unroll
            for (int mi = 0; mi < 4; mi++) {
                uint32_t off = (uint32_t)((wm + mi * 16 + a_row) * 80 + (kbase + a_kof) * 2);
                ldmx4(ah[mi], sAh + off);
                ldmx4(al[mi], sAl + off);
            }
#pragma unroll
            for (int ni2 = 0; ni2 < 2; ni2++) {
                uint32_t off = (uint32_t)((wn + ni2 * 16 + b_row) * 80 + (kbase + b_kof) * 2);
                ldmx4(bh[ni2], sBh + off);
                ldmx4(bl[ni2], sBl + off);
            }
#pragma unroll
            for (int mi = 0; mi < 4; mi++) {
#pragma unroll
                for (int ni = 0; ni < 4; ni++) {
                    const uint32_t* bhp = &bh[ni >> 1][(ni & 1) * 2];
                    const uint32_t* blp = &bl[ni >> 1][(ni & 1) * 2];
                    mma16816(acc[mi * 4 + ni], ah[mi], bhp);
                    mma16816(acc[mi * 4 + ni], al[mi], bhp);
                    mma16816(acc[mi * 4 + ni], ah[mi], blp);
                }
            }
        }
        __syncthreads();
        if (kt + 2 < kiters)
            load_stage(sb, (kt + 2) % 3, Ah, Al, Bh, Bl, m0, n0, K, (kt + 2) * 32, tid);
        CP_COMMIT();
    }

    // epilogue
#pragma unroll
    for (int mi = 0; mi < 4; mi++) {
#pragma unroll
        for (int ni = 0; ni < 4; ni++) {
            int row = m0 + wm + mi * 16 + (l >> 2);
            int col = n0 + wn + ni * 8 + (l & 3) * 2;
            float* c = C + (size_t)row * N + col;
            float2 v0; v0.x = acc[mi * 4 + ni][0]; v0.y = acc[mi * 4 + ni][1];
            float2 v1; v1.x = acc[mi * 4 + ni][2]; v1.y = acc[mi * 4 + ni][3];
            *(float2*)c = v0;
            *(float2*)(c + 8 * (size_t)N) = v1;
        }
    }
}

// ---------------- RMSNorm + mrope + transpose -------------------------------
__device__ __forceinline__ int mrope_axis(int d) {
    return d < 21 ? 0 : d < 42 ? 1 : d < 64 ? 2 : d < 85 ? 0 : d < 106 ? 1 : 2;
}

__global__ __launch_bounds__(256)
void norm_rope_kernel(const float* __restrict__ cosb, const float* __restrict__ sinb,
                      const float* __restrict__ qw,   const float* __restrict__ kw)
{
    const int m = blockIdx.x;
    const int b = m >> 11;
    const int s = m & (S_ - 1);
    const int warp = threadIdx.x >> 5;
    const int lane = threadIdx.x & 31;

#pragma unroll
    for (int it = 0; it < 4; it++) {
        int slot = warp + (it << 3);
        const float* src; float* dst; const float* w; bool rope;
        if (slot < 16) {
            src = g_q + (size_t)m * (H_ * D_) + slot * D_;
            dst = g_qr + ((size_t)(b * H_ + slot) * S_ + s) * D_;
            w = qw; rope = true;
        } else if (slot < 24) {
            int hh = slot - 16;
            src = g_k + (size_t)m * (KV_ * D_) + hh * D_;
            dst = g_kr + ((size_t)(b * KV_ + hh) * S_ + s) * D_;
            w = kw; rope = true;
        } else {
            int hh = slot - 24;
            src = g_v + (size_t)m * (KV_ * D_) + hh * D_;
            dst = g_vt + ((size_t)(b * KV_ + hh) * S_ + s) * D_;
            w = nullptr; rope = false;
        }
        float4 x4 = *(const float4*)(src + lane * 4);
        if (!rope) {
            *(float4*)(dst + lane * 4) = x4;
            continue;
        }
        float x[4] = {x4.x, x4.y, x4.z, x4.w};
        float ssum = x[0]*x[0] + x[1]*x[1] + x[2]*x[2] + x[3]*x[3];
#pragma unroll
        for (int o = 16; o > 0; o >>= 1)
            ssum += __shfl_xor_sync(0xffffffffu, ssum, o);
        float r = rsqrtf(ssum * (1.0f / 128.0f) + 1e-6f);
        float4 w4 = *(const float4*)(w + lane * 4);
        float xn[4];
        xn[0] = x[0] * r * w4.x; xn[1] = x[1] * r * w4.y;
        xn[2] = x[2] * r * w4.z; xn[3] = x[3] * r * w4.w;
        float oth[4];
#pragma unroll
        for (int j = 0; j < 4; j++)
            oth[j] = __shfl_xor_sync(0xffffffffu, xn[j], 16);
        float sgn = (lane < 16) ? -1.f : 1.f;
        int dbase = lane * 4;
        float out[4];
#pragma unroll
        for (int j = 0; j < 4; j++) {
            int d = dbase + j;
            int ax = mrope_axis(d);
            size_t ci = ((size_t)(ax * B_ + b) * S_ + s) * D_ + d;
            out[j] = xn[j] * cosb[ci] + sgn * oth[j] * sinb[ci];
        }
        *(float4*)(dst + lane * 4) = make_float4(out[0], out[1], out[2], out[3]);
    }
}

// ---------------- causal GQA flash attention (fp32) -------------------------
#define FQT_LD 68
#define FVS_LD 132
#define FPT_LD 68
#define FLASH_SMEM ((128*FQT_LD + 128*FQT_LD + 64*FVS_LD + 64*FPT_LD) * 4)

__global__ __launch_bounds__(256, 1)
void flash_kernel(const float* __restrict__ Q, const float* __restrict__ K,
                  const float* __restrict__ V, float* __restrict__ O)
{
    extern __shared__ float sm[];
    float* Qt = sm;
    float* Kt = Qt + 128 * FQT_LD;
    float* Vs = Kt + 128 * FQT_LD;
    float* Pt = Vs + 64 * FVS_LD;

    const int qt = blockIdx.x, h = blockIdx.y, b = blockIdx.z;
    const int tid = threadIdx.x;
    const int tx = tid & 15;
    const int ty = tid >> 4;
    const int q0 = qt * 64;
    const float* Qb = Q + ((size_t)(b * H_ + h) * S_ + q0) * D_;
    const float* Kb = K + ((size_t)(b * KV_ + (h >> 1)) * S_) * D_;
    const float* Vb = V + ((size_t)(b * KV_ + (h >> 1)) * S_) * D_;

#pragma unroll
    for (int it = 0; it < 8; it++) {
        int id  = tid + (it << 8);
        int row = id >> 5;
        int dq  = (id & 31) << 2;
        float4 q4 = *(const float4*)(Qb + (size_t)row * D_ + dq);
        Qt[(dq + 0) * FQT_LD + row] = q4.x;
        Qt[(dq + 1) * FQT_LD + row] = q4.y;
        Qt[(dq + 2) * FQT_LD + row] = q4.z;
        Qt[(dq + 3) * FQT_LD + row] = q4.w;
    }

    float m_i[4], l_i[4], acc[4][8];
#pragma unroll
    for (int i = 0; i < 4; i++) {
        m_i[i] = -1e30f; l_i[i] = 0.f;
#pragma unroll
        for (int j = 0; j < 8; j++) acc[i][j] = 0.f;
    }

    const float SC = 0.08838834764831845f;
    const int ntiles = qt + 1;

    for (int t = 0; t < ntiles; t++) {
        const int k0 = t * 64;
        __syncthreads();
#pragma unroll
        for (int it = 0; it < 8; it++) {
            int id  = tid + (it << 8);
            int row = id >> 5;
            int dq  = (id & 31) << 2;
            float4 k4 = *(const float4*)(Kb + (size_t)(k0 + row) * D_ + dq);
            Kt[(dq + 0) * FQT_LD + row] = k4.x;
            Kt[(dq + 1) * FQT_LD + row] = k4.y;
            Kt[(dq + 2) * FQT_LD + row] = k4.z;
            Kt[(dq + 3) * FQT_LD + row] = k4.w;
            float4 v4 = *(const float4*)(Vb + (size_t)(k0 + row) * D_ + dq);
            *(float4*)(Vs + row * FVS_LD + dq) = v4;
        }
        __syncthreads();

        float sv[4][4];
#pragma unroll
        for (int i = 0; i < 4; i++)
#pragma unroll
            for (int j = 0; j < 4; j++) sv[i][j] = 0.f;
        for (int d = 0; d < D_; d++) {
            float4 a  = *(const float4*)&Qt[d * FQT_LD + (ty << 2)];
            float4 bb = *(const float4*)&Kt[d * FQT_LD + (tx << 2)];
            float av[4] = {a.x, a.y, a.z, a.w};
            float bv[4] = {bb.x, bb.y, bb.z, bb.w};
#pragma unroll
            for (int i = 0; i < 4; i++)
#pragma unroll
                for (int j = 0; j < 4; j++)
                    sv[i][j] += av[i] * bv[j];
        }

#pragma unroll
        for (int i = 0; i < 4; i++) {
            int qi = q0 + (ty << 2) + i;
            float rm = -1e30f;
#pragma unroll
            for (int j = 0; j < 4; j++) {
                int kj = k0 + (tx << 2) + j;
                float v = (kj <= qi) ? sv[i][j] * SC : -1e30f;
                sv[i][j] = v;
                rm = fmaxf(rm, v);
            }
#pragma unroll
            for (int o = 8; o > 0; o >>= 1)
                rm = fmaxf(rm, __shfl_xor_sync(0xffffffffu, rm, o, 16));
            float mn = fmaxf(m_i[i], rm);
            float alpha = __expf(m_i[i] - mn);
            m_i[i] = mn;
            float rs = 0.f;
#pragma unroll
            for (int j = 0; j < 4; j++) {
                float p = __expf(sv[i][j] - mn);
                sv[i][j] = p;
                rs += p;
            }
#pragma unroll
            for (int o = 8; o > 0; o >>= 1)
                rs += __shfl_xor_sync(0xffffffffu, rs, o, 16);
            l_i[i] = l_i[i] * alpha + rs;
#pragma unroll
            for (int j = 0; j < 8; j++) acc[i][j] *= alpha;
        }

#pragma unroll
        for (int i = 0; i < 4; i++)
#pragma unroll
            for (int j = 0; j < 4; j++)
                Pt[((tx << 2) + j) * FPT_LD + (ty << 2) + i] = sv[i][j];
        __syncthreads();

        for (int k = 0; k < 64; k++) {
            float4 p4 = *(const float4*)&Pt[k * FPT_LD + (ty << 2)];
            float4 v0 = *(const float4*)&Vs[k * FVS_LD + (tx << 3)];
            float4 v1 = *(const float4*)&Vs[k * FVS_LD + (tx << 3) + 4];
            float pv[4] = {p4.x, p4.y, p4.z, p4.w};
            float vv[8] = {v0.x, v0.y, v0.z, v0.w, v1.x, v1.y, v1.z, v1.w};
#pragma unroll
            for (int i = 0; i < 4; i++)
#pragma unroll
                for (int j = 0; j < 8; j++)
                    acc[i][j] += pv[i] * vv[j];
        }
    }

#pragma unroll
    for (int i = 0; i < 4; i++) {
        float inv = 1.f / l_i[i];
        size_t off = ((size_t)(b * S_ + q0 + (ty << 2) + i)) * (H_ * D_) + h * D_ + (tx << 3);
        *(float4*)(O + off)     = make_float4(acc[i][0]*inv, acc[i][1]*inv, acc[i][2]*inv, acc[i][3]*inv);
        *(float4*)(O + off + 4) = make_float4(acc[i][4]*inv, acc[i][5]*inv, acc[i][6]*inv, acc[i][7]*inv);
    }
}

// ---------------- launcher ---------------------------------------------------
static void launch_split(const float* src, __nv_bfloat16* hi, __nv_bfloat16* lo, int n)
{
    int n4 = n / 4;
    split_bf16_kernel<<<(n4 + 255) / 256, 256>>>(src, hi, lo, n4);
}

extern "C" void kernel_launch(void* const* d_in, const int* in_sizes, int n_in,
                              void* d_out, int out_size)
{
    const float* hidden   = (const float*)d_in[0];
    const float* cosb     = (const float*)d_in[1];
    const float* sinb     = (const float*)d_in[2];
    const float* q_w      = (const float*)d_in[3];
    const float* k_w      = (const float*)d_in[4];
    const float* v_w      = (const float*)d_in[5];
    const float* o_w      = (const float*)d_in[6];
    const float* q_norm_w = (const float*)d_in[7];
    const float* k_norm_w = (const float*)d_in[8];
    float* out = (float*)d_out;

    float *pq, *pk, *pv, *pqr, *pkr, *pvt, *pattn;
    cudaGetSymbolAddress((void**)&pq,    g_q);
    cudaGetSymbolAddress((void**)&pk,    g_k);
    cudaGetSymbolAddress((void**)&pv,    g_v);
    cudaGetSymbolAddress((void**)&pqr,   g_qr);
    cudaGetSymbolAddress((void**)&pkr,   g_kr);
    cudaGetSymbolAddress((void**)&pvt,   g_vt);
    cudaGetSymbolAddress((void**)&pattn, g_attn);

    __nv_bfloat16 *hidh, *hidl, *qwh, *qwl, *kwh, *kwl, *vwh, *vwl, *owh, *owl, *ath, *atl;
    cudaGetSymbolAddress((void**)&hidh, g_hid_h); cudaGetSymbolAddress((void**)&hidl, g_hid_l);
    cudaGetSymbolAddress((void**)&qwh,  g_qw_h);  cudaGetSymbolAddress((void**)&qwl,  g_qw_l);
    cudaGetSymbolAddress((void**)&kwh,  g_kw_h);  cudaGetSymbolAddress((void**)&kwl,  g_kw_l);
    cudaGetSymbolAddress((void**)&vwh,  g_vw_h);  cudaGetSymbolAddress((void**)&vwl,  g_vw_l);
    cudaGetSymbolAddress((void**)&owh,  g_ow_h);  cudaGetSymbolAddress((void**)&owl,  g_ow_l);
    cudaGetSymbolAddress((void**)&ath,  g_at_h);  cudaGetSymbolAddress((void**)&atl,  g_at_l);

    cudaFuncSetAttribute(flash_kernel, cudaFuncAttributeMaxDynamicSharedMemorySize, FLASH_SMEM);
    cudaFuncSetAttribute(gemm_mma,     cudaFuncAttributeMaxDynamicSharedMemorySize, GEMM_SMEM);

    // 1) split fp32 inputs into bf16 hi/lo
    launch_split(hidden, hidh, hidl, MTOK * HID_);
    launch_split(q_w, qwh, qwl, H_*D_*HID_);
    launch_split(k_w, kwh, kwl, KV_*D_*HID_);
    launch_split(v_w, vwh, vwl, KV_*D_*HID_);
    launch_split(o_w, owh, owl, HID_*H_*D_);

    // 2) QKV projections (tensor cores via mma.sync, bf16x3)
    gemm_mma<<<dim3((H_*D_)/128,  MTOK/128), 256, GEMM_SMEM>>>(hidh, hidl, qwh, qwl, pq, H_*D_,  HID_);
    gemm_mma<<<dim3((KV_*D_)/128, MTOK/128), 256, GEMM_SMEM>>>(hidh, hidl, kwh, kwl, pk, KV_*D_, HID_);
    gemm_mma<<<dim3((KV_*D_)/128, MTOK/128), 256, GEMM_SMEM>>>(hidh, hidl, vwh, vwl, pv, KV_*D_, HID_);

    // 3) RMSNorm + mrope + layout transform
    norm_rope_kernel<<<MTOK, 256>>>(cosb, sinb, q_norm_w, k_norm_w);

    // 4) causal GQA flash attention (fp32)
    flash_kernel<<<dim3(S_ / 64, H_, B_), 256, FLASH_SMEM>>>(pqr, pkr, pvt, pattn);

    // 5) split attention output, O-projection -> d_out
    launch_split(pattn, ath, atl, MTOK * H_*D_);
    gemm_mma<<<dim3(HID_/128, MTOK/128), 256, GEMM_SMEM>>>(ath, atl, owh, owl, out, HID_, H_*D_);
}

// round 6
// speedup vs baseline: 2.5472x; 1.7052x over previous
#include <cuda_runtime.h>
#include <cuda_bf16.h>
#include <math.h>
#include <stdint.h>

// Problem constants
#define B_   2
#define S_   2048
#define HID_ 2048
#define H_   16
#define KV_  8
#define D_   128
#define MTOK (B_*S_)   // 4096 tokens

// ---------------- scratch (device globals) ----------------------------------
__device__ float g_q [MTOK * (H_*D_)];
__device__ float g_k [MTOK * (KV_*D_)];
__device__ float g_v [MTOK * (KV_*D_)];

__device__ __nv_bfloat16 g_hid_h[MTOK*HID_],   g_hid_l[MTOK*HID_];
__device__ __nv_bfloat16 g_qw_h [H_*D_*HID_],  g_qw_l [H_*D_*HID_];
__device__ __nv_bfloat16 g_kw_h [KV_*D_*HID_], g_kw_l [KV_*D_*HID_];
__device__ __nv_bfloat16 g_vw_h [KV_*D_*HID_], g_vw_l [KV_*D_*HID_];
__device__ __nv_bfloat16 g_ow_h [HID_*H_*D_],  g_ow_l [HID_*H_*D_];

// roped/normed operands for flash (bf16 hi/lo), [B,H|KV,S,D]
__device__ __nv_bfloat16 g_qh[B_*H_*S_*D_],  g_ql[B_*H_*S_*D_];
__device__ __nv_bfloat16 g_kh[B_*KV_*S_*D_], g_kl[B_*KV_*S_*D_];
__device__ __nv_bfloat16 g_vh[B_*KV_*S_*D_], g_vl[B_*KV_*S_*D_];
// attention output (bf16 hi/lo), [B*S, H*D]
__device__ __nv_bfloat16 g_at_h[MTOK*H_*D_], g_at_l[MTOK*H_*D_];

// ======================= PTX helpers (sm_80-era) ===========================
__device__ __forceinline__ uint32_t smem_u32(const void* p) {
    return (uint32_t)__cvta_generic_to_shared(p);
}
__device__ __forceinline__ void cpasync16(uint32_t dst, const void* src) {
    asm volatile("cp.async.cg.shared.global [%0], [%1], 16;" :: "r"(dst), "l"(src));
}
#define CP_COMMIT() asm volatile("cp.async.commit_group;" ::: "memory")
#define CP_WAIT1()  asm volatile("cp.async.wait_group 1;" ::: "memory")
#define CP_WAIT0()  asm volatile("cp.async.wait_group 0;" ::: "memory")

__device__ __forceinline__ void ldmx4(uint32_t* r, uint32_t addr) {
    asm volatile("ldmatrix.sync.aligned.m8n8.x4.shared.b16 {%0,%1,%2,%3}, [%4];"
                 : "=r"(r[0]), "=r"(r[1]), "=r"(r[2]), "=r"(r[3]) : "r"(addr));
}
__device__ __forceinline__ void ldmx4t(uint32_t* r, uint32_t addr) {
    asm volatile("ldmatrix.sync.aligned.m8n8.x4.trans.shared.b16 {%0,%1,%2,%3}, [%4];"
                 : "=r"(r[0]), "=r"(r[1]), "=r"(r[2]), "=r"(r[3]) : "r"(addr));
}
__device__ __forceinline__ void mma16816(float* d, const uint32_t* a, const uint32_t* b) {
    asm volatile("mma.sync.aligned.m16n8k16.row.col.f32.bf16.bf16.f32 "
                 "{%0,%1,%2,%3}, {%4,%5,%6,%7}, {%8,%9}, {%0,%1,%2,%3};"
                 : "+f"(d[0]), "+f"(d[1]), "+f"(d[2]), "+f"(d[3])
                 : "r"(a[0]), "r"(a[1]), "r"(a[2]), "r"(a[3]), "r"(b[0]), "r"(b[1]));
}
__device__ __forceinline__ uint32_t packbf(float x, float y) {
    __nv_bfloat162 t;
    t.x = __float2bfloat16_rn(x); t.y = __float2bfloat16_rn(y);
    return *(uint32_t*)&t;
}
__device__ __forceinline__ float fexp(float x) {
    return __expf(fmaxf(x, -80.0f));   // range-safe exp
}

// ======================= fp32 -> bf16 hi/lo split ==========================
__global__ __launch_bounds__(256)
void split_bf16_kernel(const float* __restrict__ src,
                       __nv_bfloat16* __restrict__ hi,
                       __nv_bfloat16* __restrict__ lo, int n4)
{
    int i = blockIdx.x * blockDim.x + threadIdx.x;
    if (i >= n4) return;
    float4 x = ((const float4*)src)[i];
    float xs[4] = {x.x, x.y, x.z, x.w};
    __nv_bfloat16 h[4], l[4];
#pragma unroll
    for (int j = 0; j < 4; j++) {
        h[j] = __float2bfloat16_rn(xs[j]);
        l[j] = __float2bfloat16_rn(xs[j] - __bfloat162float(h[j]));
    }
    __nv_bfloat162 h0; h0.x = h[0]; h0.y = h[1];
    __nv_bfloat162 h1; h1.x = h[2]; h1.y = h[3];
    __nv_bfloat162 l0; l0.x = l[0]; l0.y = l[1];
    __nv_bfloat162 l1; l1.x = l[2]; l1.y = l[3];
    ((__nv_bfloat162*)hi)[i*2 + 0] = h0;
    ((__nv_bfloat162*)hi)[i*2 + 1] = h1;
    ((__nv_bfloat162*)lo)[i*2 + 0] = l0;
    ((__nv_bfloat162*)lo)[i*2 + 1] = l1;
}

// ======================= mma.sync bf16x3 GEMM (NT) =========================
#define LDT   40
#define TILE_B (128*LDT*2)
#define STG_B  (4*TILE_B)
#define NSTG  3
#define GEMM_SMEM (NSTG*STG_B)

__device__ __forceinline__ void load_stage(
    uint32_t sbase, int stg,
    const __nv_bfloat16* __restrict__ Ah, const __nv_bfloat16* __restrict__ Al,
    const __nv_bfloat16* __restrict__ Bh, const __nv_bfloat16* __restrict__ Bl,
    int m0, int n0, int K, int k0, int tid)
{
    uint32_t sd = sbase + stg * STG_B;
#pragma unroll
    for (int i = 0; i < 8; i++) {
        int chunk = i * 256 + tid;
        int tile  = chunk >> 9;
        int idx   = chunk & 511;
        int row   = idx >> 2;
        int cseg  = idx & 3;
        const __nv_bfloat16* g = (tile == 0) ? Ah : (tile == 1) ? Al : (tile == 2) ? Bh : Bl;
        int grow = ((tile < 2) ? m0 : n0) + row;
        const char* src = (const char*)(g + (size_t)grow * K + k0) + cseg * 16;
        cpasync16(sd + tile * TILE_B + row * 80 + cseg * 16, src);
    }
}

__global__ __launch_bounds__(256, 1)
void gemm_mma(const __nv_bfloat16* __restrict__ Ah, const __nv_bfloat16* __restrict__ Al,
              const __nv_bfloat16* __restrict__ Bh, const __nv_bfloat16* __restrict__ Bl,
              float* __restrict__ C, int N, int K)
{
    extern __shared__ char dsm[];
    const uint32_t sb = smem_u32(dsm);
    const int tid = threadIdx.x;
    const int w = tid >> 5;
    const int l = tid & 31;
    const int wm = (w >> 2) * 64;
    const int wn = (w & 3) * 32;
    const int m0 = blockIdx.y * 128;
    const int n0 = blockIdx.x * 128;
    const int kiters = K / 32;

    load_stage(sb, 0, Ah, Al, Bh, Bl, m0, n0, K, 0, tid);  CP_COMMIT();
    load_stage(sb, 1, Ah, Al, Bh, Bl, m0, n0, K, 32, tid); CP_COMMIT();

    float acc[16][4];
#pragma unroll
    for (int i = 0; i < 16; i++)
#pragma unroll
        for (int j = 0; j < 4; j++) acc[i][j] = 0.f;

    const int a_row = (l & 15);
    const int a_kof = (l >> 4) * 8;
    const int b_row = (l & 7) + ((l >> 4) & 1) * 8;
    const int b_kof = ((l >> 3) & 1) * 8;

    for (int kt = 0; kt < kiters; kt++) {
        CP_WAIT1();
        __syncthreads();
        const uint32_t st = sb + (kt % 3) * STG_B;
        const uint32_t sAh = st;
        const uint32_t sAl = st + TILE_B;
        const uint32_t sBh = st + 2 * TILE_B;
        const uint32_t sBl = st + 3 * TILE_B;

#pragma unroll
        for (int ks = 0; ks < 2; ks++) {
            const int kbase = ks * 16;
            uint32_t ah[4][4], al[4][4], bh[2][4], bl[2][4];
#pragma unroll
            for (int mi = 0; mi < 4; mi++) {
                uint32_t off = (uint32_t)((wm + mi * 16 + a_row) * 80 + (kbase + a_kof) * 2);
                ldmx4(ah[mi], sAh + off);
                ldmx4(al[mi], sAl + off);
            }
#pragma unroll
            for (int ni2 = 0; ni2 < 2; ni2++) {
                uint32_t off = (uint32_t)((wn + ni2 * 16 + b_row) * 80 + (kbase + b_kof) * 2);
                ldmx4(bh[ni2], sBh + off);
                ldmx4(bl[ni2], sBl + off);
            }
#pragma unroll
            for (int mi = 0; mi < 4; mi++) {
#pragma unroll
                for (int ni = 0; ni < 4; ni++) {
                    const uint32_t* bhp = &bh[ni >> 1][(ni & 1) * 2];
                    const uint32_t* blp = &bl[ni >> 1][(ni & 1) * 2];
                    mma16816(acc[mi * 4 + ni], ah[mi], bhp);
                    mma16816(acc[mi * 4 + ni], al[mi], bhp);
                    mma16816(acc[mi * 4 + ni], ah[mi], blp);
                }
            }
        }
        __syncthreads();
        if (kt + 2 < kiters)
            load_stage(sb, (kt + 2) % 3, Ah, Al, Bh, Bl, m0, n0, K, (kt + 2) * 32, tid);
        CP_COMMIT();
    }

#pragma unroll
    for (int mi = 0; mi < 4; mi++) {
#pragma unroll
        for (int ni = 0; ni < 4; ni++) {
            int row = m0 + wm + mi * 16 + (l >> 2);
            int col = n0 + wn + ni * 8 + (l & 3) * 2;
            float* c = C + (size_t)row * N + col;
            float2 v0; v0.x = acc[mi * 4 + ni][0]; v0.y = acc[mi * 4 + ni][1];
            float2 v1; v1.x = acc[mi * 4 + ni][2]; v1.y = acc[mi * 4 + ni][3];
            *(float2*)c = v0;
            *(float2*)(c + 8 * (size_t)N) = v1;
        }
    }
}

// ---------------- RMSNorm + mrope + bf16 hi/lo split ------------------------
__device__ __forceinline__ int mrope_axis(int d) {
    return d < 21 ? 0 : d < 42 ? 1 : d < 64 ? 2 : d < 85 ? 0 : d < 106 ? 1 : 2;
}

__global__ __launch_bounds__(256)
void norm_rope_kernel(const float* __restrict__ cosb, const float* __restrict__ sinb,
                      const float* __restrict__ qw,   const float* __restrict__ kw)
{
    const int m = blockIdx.x;
    const int b = m >> 11;
    const int s = m & (S_ - 1);
    const int warp = threadIdx.x >> 5;
    const int lane = threadIdx.x & 31;
    const float SC = 0.08838834764831845f;  // 128^-0.5 folded into Q

#pragma unroll
    for (int it = 0; it < 4; it++) {
        int slot = warp + (it << 3);
        const float* src; __nv_bfloat16 *dh, *dl; const float* w; bool rope; float scale;
        if (slot < 16) {
            src = g_q + (size_t)m * (H_ * D_) + slot * D_;
            size_t o = ((size_t)(b * H_ + slot) * S_ + s) * D_;
            dh = g_qh + o; dl = g_ql + o;
            w = qw; rope = true; scale = SC;
        } else if (slot < 24) {
            int hh = slot - 16;
            src = g_k + (size_t)m * (KV_ * D_) + hh * D_;
            size_t o = ((size_t)(b * KV_ + hh) * S_ + s) * D_;
            dh = g_kh + o; dl = g_kl + o;
            w = kw; rope = true; scale = 1.f;
        } else {
            int hh = slot - 24;
            src = g_v + (size_t)m * (KV_ * D_) + hh * D_;
            size_t o = ((size_t)(b * KV_ + hh) * S_ + s) * D_;
            dh = g_vh + o; dl = g_vl + o;
            w = nullptr; rope = false; scale = 1.f;
        }
        float4 x4 = *(const float4*)(src + lane * 4);
        float out[4] = {x4.x, x4.y, x4.z, x4.w};
        if (rope) {
            float x[4] = {out[0], out[1], out[2], out[3]};
            float ssum = x[0]*x[0] + x[1]*x[1] + x[2]*x[2] + x[3]*x[3];
#pragma unroll
            for (int o2 = 16; o2 > 0; o2 >>= 1)
                ssum += __shfl_xor_sync(0xffffffffu, ssum, o2);
            float r = rsqrtf(ssum * (1.0f / 128.0f) + 1e-6f);
            float4 w4 = *(const float4*)(w + lane * 4);
            float xn[4];
            xn[0] = x[0] * r * w4.x; xn[1] = x[1] * r * w4.y;
            xn[2] = x[2] * r * w4.z; xn[3] = x[3] * r * w4.w;
            float oth[4];
#pragma unroll
            for (int j = 0; j < 4; j++)
                oth[j] = __shfl_xor_sync(0xffffffffu, xn[j], 16);
            float sgn = (lane < 16) ? -1.f : 1.f;
            int dbase = lane * 4;
#pragma unroll
            for (int j = 0; j < 4; j++) {
                int d = dbase + j;
                int ax = mrope_axis(d);
                size_t ci = ((size_t)(ax * B_ + b) * S_ + s) * D_ + d;
                out[j] = (xn[j] * cosb[ci] + sgn * oth[j] * sinb[ci]) * scale;
            }
        }
        __nv_bfloat16 h[4], lo[4];
#pragma unroll
        for (int j = 0; j < 4; j++) {
            h[j]  = __float2bfloat16_rn(out[j]);
            lo[j] = __float2bfloat16_rn(out[j] - __bfloat162float(h[j]));
        }
        __nv_bfloat162* ph = (__nv_bfloat162*)(dh + lane * 4);
        __nv_bfloat162* pl = (__nv_bfloat162*)(dl + lane * 4);
        __nv_bfloat162 t;
        t.x = h[0];  t.y = h[1];  ph[0] = t;
        t.x = h[2];  t.y = h[3];  ph[1] = t;
        t.x = lo[0]; t.y = lo[1]; pl[0] = t;
        t.x = lo[2]; t.y = lo[3]; pl[1] = t;
    }
}

// ---------------- causal GQA flash attention (mma.sync bf16x3) --------------
// CTA: 64 q rows, 128 threads. K-tile 64. D=128. K/V double-buffered.
// P goes through SMEM (C-fragment store -> A-fragment ldmatrix load).
#define FSTR 136                 // K/V/Q smem row stride (elems), 272B
#define PSTR 72                  // P smem row stride (elems), 144B
#define TILE_E (64*FSTR)         // 8704 elems per tile
#define FLASH_SMEM ((10*TILE_E + 2*64*PSTR)*2)   // 192512 bytes
#define MASKV (-30000.0f)

__device__ __forceinline__ void load_kv_stage(
    __nv_bfloat16* fsb, int st, int k0,
    const __nv_bfloat16* Kh, const __nv_bfloat16* Kl,
    const __nv_bfloat16* Vh, const __nv_bfloat16* Vl, int tid)
{
    __nv_bfloat16* kh = fsb + (2 + st*4) * TILE_E;
    __nv_bfloat16* kl = kh + TILE_E;
    __nv_bfloat16* vh = kl + TILE_E;
    __nv_bfloat16* vl = vh + TILE_E;
    // 64 rows x 128 elems = 64 x 16 chunks of 16B -> 1024 chunks per array
#pragma unroll
    for (int i = 0; i < 8; i++) {
        int c = tid + i * 128;          // 0..1023
        int r = c >> 4, cs = c & 15;    // row 0..63, seg 0..15
        size_t go = (size_t)(k0 + r) * D_ + cs * 8;
        uint32_t so = (uint32_t)(r * FSTR + cs * 8);
        cpasync16(smem_u32(kh + so), Kh + go);
        cpasync16(smem_u32(kl + so), Kl + go);
        cpasync16(smem_u32(vh + so), Vh + go);
        cpasync16(smem_u32(vl + so), Vl + go);
    }
}

__global__ __launch_bounds__(128, 1)
void flash_mma(__nv_bfloat16* __restrict__ Oh, __nv_bfloat16* __restrict__ Ol)
{
    extern __shared__ __nv_bfloat16 fsb[];
    __nv_bfloat16* sQh = fsb;
    __nv_bfloat16* sQl = fsb + TILE_E;
    __nv_bfloat16* sPh = fsb + 10 * TILE_E;
    __nv_bfloat16* sPl = sPh + 64 * PSTR;

    const int qt = blockIdx.x, h = blockIdx.y, b = blockIdx.z;
    const int tid = threadIdx.x;
    const int w = tid >> 5;
    const int l = tid & 31;
    const int q0 = qt * 64;

    const __nv_bfloat16* Qbh = g_qh + ((size_t)(b * H_ + h) * S_ + q0) * D_;
    const __nv_bfloat16* Qbl = g_ql + ((size_t)(b * H_ + h) * S_ + q0) * D_;
    const __nv_bfloat16* Kbh = g_kh + (size_t)(b * KV_ + (h >> 1)) * S_ * D_;
    const __nv_bfloat16* Kbl = g_kl + (size_t)(b * KV_ + (h >> 1)) * S_ * D_;
    const __nv_bfloat16* Vbh = g_vh + (size_t)(b * KV_ + (h >> 1)) * S_ * D_;
    const __nv_bfloat16* Vbl = g_vl + (size_t)(b * KV_ + (h >> 1)) * S_ * D_;

    // prologue: Q (64 rows x 16 segs = 1024 chunks per array) + KV(tile 0)
#pragma unroll
    for (int i = 0; i < 8; i++) {
        int c = tid + i * 128;
        int r = c >> 4, cs = c & 15;
        size_t go = (size_t)r * D_ + cs * 8;
        uint32_t so = (uint32_t)(r * FSTR + cs * 8);
        cpasync16(smem_u32(sQh + so), Qbh + go);
        cpasync16(smem_u32(sQl + so), Qbl + go);
    }
    load_kv_stage(fsb, 0, 0, Kbh, Kbl, Vbh, Vbl, tid);
    CP_COMMIT();

    float o[16][4];
#pragma unroll
    for (int i = 0; i < 16; i++)
#pragma unroll
        for (int j = 0; j < 4; j++) o[i][j] = 0.f;
    float mrow[2] = {MASKV, MASKV};
    float lrow[2] = {0.f, 0.f};

    const int r0 = l >> 2;
    const int a_row = (l & 15);
    const int a_kof = (l >> 4) * 8;
    const int b_row = (l & 7) + ((l >> 4) & 1) * 8;
    const int b_kof = ((l >> 3) & 1) * 8;
    const int v_row = (l & 15);
    const int v_cof = (l >> 4) * 8;

    for (int t = 0; t <= qt; t++) {
        const int k0 = t * 64;
        const int st = t & 1;
        if (t < qt) {
            load_kv_stage(fsb, st ^ 1, (t + 1) * 64, Kbh, Kbl, Vbh, Vbl, tid);
            CP_COMMIT();
            CP_WAIT1();
        } else {
            CP_WAIT0();
        }
        __syncthreads();

        __nv_bfloat16* sKh = fsb + (2 + st*4) * TILE_E;
        __nv_bfloat16* sKl = sKh + TILE_E;
        __nv_bfloat16* sVh = sKl + TILE_E;
        __nv_bfloat16* sVl = sVh + TILE_E;

        // ---- S = Q K^T (64x64), warp handles rows 16w..16w+15 ----
        float s[8][4];
#pragma unroll
        for (int i = 0; i < 8; i++)
#pragma unroll
            for (int j = 0; j < 4; j++) s[i][j] = 0.f;

#pragma unroll
        for (int ks = 0; ks < 8; ks++) {
            uint32_t aoff = (uint32_t)((16 * w + a_row) * FSTR + ks * 16 + a_kof) * 2;
            uint32_t ah[4], al[4];
            ldmx4(ah, smem_u32(sQh) + aoff);
            ldmx4(al, smem_u32(sQl) + aoff);
#pragma unroll
            for (int ng = 0; ng < 4; ng++) {
                uint32_t boff = (uint32_t)((16 * ng + b_row) * FSTR + ks * 16 + b_kof) * 2;
                uint32_t bh[4], bl[4];
                ldmx4(bh, smem_u32(sKh) + boff);
                ldmx4(bl, smem_u32(sKl) + boff);
                mma16816(s[2*ng],   ah, &bh[0]);
                mma16816(s[2*ng],   al, &bh[0]);
                mma16816(s[2*ng],   ah, &bl[0]);
                mma16816(s[2*ng+1], ah, &bh[2]);
                mma16816(s[2*ng+1], al, &bh[2]);
                mma16816(s[2*ng+1], ah, &bl[2]);
            }
        }

        // ---- causal mask (diagonal tile only) ----
        if (t == qt) {
            int grow0 = q0 + 16 * w + r0;
            int grow1 = grow0 + 8;
#pragma unroll
            for (int nt = 0; nt < 8; nt++) {
                int col = k0 + nt * 8 + (l & 3) * 2;
                if (col > grow0)     s[nt][0] = MASKV;
                if (col + 1 > grow0) s[nt][1] = MASKV;
                if (col > grow1)     s[nt][2] = MASKV;
                if (col + 1 > grow1) s[nt][3] = MASKV;
            }
        }

        // ---- online softmax (range-safe) ----
        float rm0 = MASKV, rm1 = MASKV;
#pragma unroll
        for (int nt = 0; nt < 8; nt++) {
            rm0 = fmaxf(rm0, fmaxf(s[nt][0], s[nt][1]));
            rm1 = fmaxf(rm1, fmaxf(s[nt][2], s[nt][3]));
        }
        rm0 = fmaxf(rm0, __shfl_xor_sync(0xffffffffu, rm0, 1));
        rm0 = fmaxf(rm0, __shfl_xor_sync(0xffffffffu, rm0, 2));
        rm1 = fmaxf(rm1, __shfl_xor_sync(0xffffffffu, rm1, 1));
        rm1 = fmaxf(rm1, __shfl_xor_sync(0xffffffffu, rm1, 2));

        float mn0 = fmaxf(mrow[0], rm0);
        float mn1 = fmaxf(mrow[1], rm1);
        float alpha0 = fexp(mrow[0] - mn0);
        float alpha1 = fexp(mrow[1] - mn1);
        mrow[0] = mn0; mrow[1] = mn1;

        float rs0 = 0.f, rs1 = 0.f;
#pragma unroll
        for (int nt = 0; nt < 8; nt++) {
            s[nt][0] = fexp(s[nt][0] - mn0);
            s[nt][1] = fexp(s[nt][1] - mn0);
            s[nt][2] = fexp(s[nt][2] - mn1);
            s[nt][3] = fexp(s[nt][3] - mn1);
            rs0 += s[nt][0] + s[nt][1];
            rs1 += s[nt][2] + s[nt][3];
        }
        rs0 += __shfl_xor_sync(0xffffffffu, rs0, 1);
        rs0 += __shfl_xor_sync(0xffffffffu, rs0, 2);
        rs1 += __shfl_xor_sync(0xffffffffu, rs1, 1);
        rs1 += __shfl_xor_sync(0xffffffffu, rs1, 2);
        lrow[0] = lrow[0] * alpha0 + rs0;
        lrow[1] = lrow[1] * alpha1 + rs1;

#pragma unroll
        for (int nt = 0; nt < 16; nt++) {
            o[nt][0] *= alpha0; o[nt][1] *= alpha0;
            o[nt][2] *= alpha1; o[nt][3] *= alpha1;
        }

        // ---- store P (bf16 hi/lo) in C-fragment layout; per-warp private rows ----
        {
            int prow0 = 16 * w + r0;
#pragma unroll
            for (int nt = 0; nt < 8; nt++) {
                int pcol = nt * 8 + (l & 3) * 2;
                uint32_t ph0 = packbf(s[nt][0], s[nt][1]);
                __nv_bfloat162 th0 = *(__nv_bfloat162*)&ph0;
                uint32_t pl0 = packbf(s[nt][0] - __bfloat162float(th0.x),
                                      s[nt][1] - __bfloat162float(th0.y));
                *(uint32_t*)(sPh + prow0 * PSTR + pcol) = ph0;
                *(uint32_t*)(sPl + prow0 * PSTR + pcol) = pl0;
                uint32_t ph1 = packbf(s[nt][2], s[nt][3]);
                __nv_bfloat162 th1 = *(__nv_bfloat162*)&ph1;
                uint32_t pl1 = packbf(s[nt][2] - __bfloat162float(th1.x),
                                      s[nt][3] - __bfloat162float(th1.y));
                *(uint32_t*)(sPh + (prow0 + 8) * PSTR + pcol) = ph1;
                *(uint32_t*)(sPl + (prow0 + 8) * PSTR + pcol) = pl1;
            }
        }
        __syncwarp();

        // ---- O += P V : P A-fragments from smem, V B-fragments via trans ----
#pragma unroll
        for (int ks = 0; ks < 4; ks++) {
            uint32_t poff = (uint32_t)((16 * w + a_row) * PSTR + ks * 16 + a_kof) * 2;
            uint32_t pah[4], pal[4];
            ldmx4(pah, smem_u32(sPh) + poff);
            ldmx4(pal, smem_u32(sPl) + poff);
#pragma unroll
            for (int dg = 0; dg < 8; dg++) {
                uint32_t voff = (uint32_t)((ks * 16 + v_row) * FSTR + dg * 16 + v_cof) * 2;
                uint32_t vh[4], vl[4];
                ldmx4t(vh, smem_u32(sVh) + voff);
                ldmx4t(vl, smem_u32(sVl) + voff);
                mma16816(o[2*dg],   pah, &vh[0]);
                mma16816(o[2*dg],   pal, &vh[0]);
                mma16816(o[2*dg],   pah, &vl[0]);
                mma16816(o[2*dg+1], pah, &vh[2]);
                mma16816(o[2*dg+1], pal, &vh[2]);
                mma16816(o[2*dg+1], pah, &vl[2]);
            }
        }
        __syncthreads();   // all reads of stage st done before it is refilled
    }

    // ---- epilogue ----
    float inv0 = 1.f / lrow[0];
    float inv1 = 1.f / lrow[1];
    size_t row0 = (size_t)b * S_ + q0 + 16 * w + r0;
    size_t row1 = row0 + 8;
    int colb = h * D_ + (l & 3) * 2;
#pragma unroll
    for (int nt = 0; nt < 16; nt++) {
        int col = colb + nt * 8;
        float v0 = o[nt][0] * inv0, v1 = o[nt][1] * inv0;
        float v2 = o[nt][2] * inv1, v3 = o[nt][3] * inv1;
        uint32_t h0 = packbf(v0, v1);
        __nv_bfloat162 th = *(__nv_bfloat162*)&h0;
        uint32_t lo0 = packbf(v0 - __bfloat162float(th.x), v1 - __bfloat162float(th.y));
        *(uint32_t*)(Oh + row0 * (H_*D_) + col) = h0;
        *(uint32_t*)(Ol + row0 * (H_*D_) + col) = lo0;
        uint32_t h1 = packbf(v2, v3);
        __nv_bfloat162 th1 = *(__nv_bfloat162*)&h1;
        uint32_t lo1 = packbf(v2 - __bfloat162float(th1.x), v3 - __bfloat162float(th1.y));
        *(uint32_t*)(Oh + row1 * (H_*D_) + col) = h1;
        *(uint32_t*)(Ol + row1 * (H_*D_) + col) = lo1;
    }
}

// ---------------- launcher ---------------------------------------------------
static void launch_split(const float* src, __nv_bfloat16* hi, __nv_bfloat16* lo, int n)
{
    int n4 = n / 4;
    split_bf16_kernel<<<(n4 + 255) / 256, 256>>>(src, hi, lo, n4);
}

extern "C" void kernel_launch(void* const* d_in, const int* in_sizes, int n_in,
                              void* d_out, int out_size)
{
    const float* hidden   = (const float*)d_in[0];
    const float* cosb     = (const float*)d_in[1];
    const float* sinb     = (const float*)d_in[2];
    const float* q_w      = (const float*)d_in[3];
    const float* k_w      = (const float*)d_in[4];
    const float* v_w      = (const float*)d_in[5];
    const float* o_w      = (const float*)d_in[6];
    const float* q_norm_w = (const float*)d_in[7];
    const float* k_norm_w = (const float*)d_in[8];
    float* out = (float*)d_out;

    float *pq, *pk, *pv;
    cudaGetSymbolAddress((void**)&pq, g_q);
    cudaGetSymbolAddress((void**)&pk, g_k);
    cudaGetSymbolAddress((void**)&pv, g_v);

    __nv_bfloat16 *hidh, *hidl, *qwh, *qwl, *kwh, *kwl, *vwh, *vwl, *owh, *owl, *ath, *atl;
    cudaGetSymbolAddress((void**)&hidh, g_hid_h); cudaGetSymbolAddress((void**)&hidl, g_hid_l);
    cudaGetSymbolAddress((void**)&qwh,  g_qw_h);  cudaGetSymbolAddress((void**)&qwl,  g_qw_l);
    cudaGetSymbolAddress((void**)&kwh,  g_kw_h);  cudaGetSymbolAddress((void**)&kwl,  g_kw_l);
    cudaGetSymbolAddress((void**)&vwh,  g_vw_h);  cudaGetSymbolAddress((void**)&vwl,  g_vw_l);
    cudaGetSymbolAddress((void**)&owh,  g_ow_h);  cudaGetSymbolAddress((void**)&owl,  g_ow_l);
    cudaGetSymbolAddress((void**)&ath,  g_at_h);  cudaGetSymbolAddress((void**)&atl,  g_at_l);

    cudaFuncSetAttribute(gemm_mma,  cudaFuncAttributeMaxDynamicSharedMemorySize, GEMM_SMEM);
    cudaFuncSetAttribute(flash_mma, cudaFuncAttributeMaxDynamicSharedMemorySize, FLASH_SMEM);

    // 1) split fp32 inputs into bf16 hi/lo
    launch_split(hidden, hidh, hidl, MTOK * HID_);
    launch_split(q_w, qwh, qwl, H_*D_*HID_);
    launch_split(k_w, kwh, kwl, KV_*D_*HID_);
    launch_split(v_w, vwh, vwl, KV_*D_*HID_);
    launch_split(o_w, owh, owl, HID_*H_*D_);

    // 2) QKV projections (tensor cores, bf16x3)
    gemm_mma<<<dim3((H_*D_)/128,  MTOK/128), 256, GEMM_SMEM>>>(hidh, hidl, qwh, qwl, pq, H_*D_,  HID_);
    gemm_mma<<<dim3((KV_*D_)/128, MTOK/128), 256, GEMM_SMEM>>>(hidh, hidl, kwh, kwl, pk, KV_*D_, HID_);
    gemm_mma<<<dim3((KV_*D_)/128, MTOK/128), 256, GEMM_SMEM>>>(hidh, hidl, vwh, vwl, pv, KV_*D_, HID_);

    // 3) RMSNorm + mrope + split to bf16 hi/lo (Q pre-scaled by 1/sqrt(D))
    norm_rope_kernel<<<MTOK, 256>>>(cosb, sinb, q_norm_w, k_norm_w);

    // 4) causal GQA flash attention (tensor cores, bf16x3) -> bf16 hi/lo out
    flash_mma<<<dim3(S_ / 64, H_, B_), 128, FLASH_SMEM>>>(ath, atl);

    // 5) O-projection -> d_out
    gemm_mma<<<dim3(HID_/128, MTOK/128), 256, GEMM_SMEM>>>(ath, atl, owh, owl, out, HID_, H_*D_);
}

// round 7
// speedup vs baseline: 2.7270x; 1.0706x over previous
#include <cuda_runtime.h>
#include <cuda_bf16.h>
#include <math.h>
#include <stdint.h>

// Problem constants
#define B_   2
#define S_   2048
#define HID_ 2048
#define H_   16
#define KV_  8
#define D_   128
#define MTOK (B_*S_)   // 4096 tokens
#define NQKV 4096      // H*D + KV*D + KV*D

// ---------------- scratch (device globals) ----------------------------------
__device__ float g_qkv[MTOK * NQKV];   // fused QKV projection output

__device__ __nv_bfloat16 g_hid_h[MTOK*HID_],  g_hid_l[MTOK*HID_];
__device__ __nv_bfloat16 g_w_h [NQKV*HID_],   g_w_l [NQKV*HID_];   // q|k|v weights concat
__device__ __nv_bfloat16 g_ow_h[HID_*H_*D_],  g_ow_l[HID_*H_*D_];

// roped/normed operands for flash (bf16 hi/lo), [B,H|KV,S,D]
__device__ __nv_bfloat16 g_qh[B_*H_*S_*D_],  g_ql[B_*H_*S_*D_];
__device__ __nv_bfloat16 g_kh[B_*KV_*S_*D_], g_kl[B_*KV_*S_*D_];
__device__ __nv_bfloat16 g_vh[B_*KV_*S_*D_], g_vl[B_*KV_*S_*D_];
// attention output (bf16 hi/lo), [B*S, H*D]
__device__ __nv_bfloat16 g_at_h[MTOK*H_*D_], g_at_l[MTOK*H_*D_];

// ======================= PTX helpers (sm_80-era) ===========================
__device__ __forceinline__ uint32_t smem_u32(const void* p) {
    return (uint32_t)__cvta_generic_to_shared(p);
}
__device__ __forceinline__ void cpasync16(uint32_t dst, const void* src) {
    asm volatile("cp.async.cg.shared.global [%0], [%1], 16;" :: "r"(dst), "l"(src));
}
#define CP_COMMIT() asm volatile("cp.async.commit_group;" ::: "memory")
#define CP_WAIT1()  asm volatile("cp.async.wait_group 1;" ::: "memory")
#define CP_WAIT0()  asm volatile("cp.async.wait_group 0;" ::: "memory")

__device__ __forceinline__ void ldmx4(uint32_t* r, uint32_t addr) {
    asm volatile("ldmatrix.sync.aligned.m8n8.x4.shared.b16 {%0,%1,%2,%3}, [%4];"
                 : "=r"(r[0]), "=r"(r[1]), "=r"(r[2]), "=r"(r[3]) : "r"(addr));
}
__device__ __forceinline__ void ldmx4t(uint32_t* r, uint32_t addr) {
    asm volatile("ldmatrix.sync.aligned.m8n8.x4.trans.shared.b16 {%0,%1,%2,%3}, [%4];"
                 : "=r"(r[0]), "=r"(r[1]), "=r"(r[2]), "=r"(r[3]) : "r"(addr));
}
__device__ __forceinline__ void mma16816(float* d, const uint32_t* a, const uint32_t* b) {
    asm volatile("mma.sync.aligned.m16n8k16.row.col.f32.bf16.bf16.f32 "
                 "{%0,%1,%2,%3}, {%4,%5,%6,%7}, {%8,%9}, {%0,%1,%2,%3};"
                 : "+f"(d[0]), "+f"(d[1]), "+f"(d[2]), "+f"(d[3])
                 : "r"(a[0]), "r"(a[1]), "r"(a[2]), "r"(a[3]), "r"(b[0]), "r"(b[1]));
}
__device__ __forceinline__ uint32_t packbf(float x, float y) {
    __nv_bfloat162 t;
    t.x = __float2bfloat16_rn(x); t.y = __float2bfloat16_rn(y);
    return *(uint32_t*)&t;
}
__device__ __forceinline__ float fexp(float x) {
    return __expf(fmaxf(x, -80.0f));   // range-safe exp
}

// ======================= fp32 -> bf16 hi/lo split ==========================
__global__ __launch_bounds__(256)
void split_bf16_kernel(const float* __restrict__ src,
                       __nv_bfloat16* __restrict__ hi,
                       __nv_bfloat16* __restrict__ lo, int n4)
{
    int i = blockIdx.x * blockDim.x + threadIdx.x;
    if (i >= n4) return;
    float4 x = ((const float4*)src)[i];
    float xs[4] = {x.x, x.y, x.z, x.w};
    __nv_bfloat16 h[4], l[4];
#pragma unroll
    for (int j = 0; j < 4; j++) {
        h[j] = __float2bfloat16_rn(xs[j]);
        l[j] = __float2bfloat16_rn(xs[j] - __bfloat162float(h[j]));
    }
    __nv_bfloat162 h0; h0.x = h[0]; h0.y = h[1];
    __nv_bfloat162 h1; h1.x = h[2]; h1.y = h[3];
    __nv_bfloat162 l0; l0.x = l[0]; l0.y = l[1];
    __nv_bfloat162 l1; l1.x = l[2]; l1.y = l[3];
    ((__nv_bfloat162*)hi)[i*2 + 0] = h0;
    ((__nv_bfloat162*)hi)[i*2 + 1] = h1;
    ((__nv_bfloat162*)lo)[i*2 + 0] = l0;
    ((__nv_bfloat162*)lo)[i*2 + 1] = l1;
}

// ======================= mma.sync bf16x3 GEMM (NT) =========================
#define LDT   40
#define TILE_B (128*LDT*2)
#define STG_B  (4*TILE_B)
#define NSTG  3
#define GEMM_SMEM (NSTG*STG_B)

__device__ __forceinline__ void load_stage(
    uint32_t sbase, int stg,
    const __nv_bfloat16* __restrict__ Ah, const __nv_bfloat16* __restrict__ Al,
    const __nv_bfloat16* __restrict__ Bh, const __nv_bfloat16* __restrict__ Bl,
    int m0, int n0, int K, int k0, int tid)
{
    uint32_t sd = sbase + stg * STG_B;
#pragma unroll
    for (int i = 0; i < 8; i++) {
        int chunk = i * 256 + tid;
        int tile  = chunk >> 9;
        int idx   = chunk & 511;
        int row   = idx >> 2;
        int cseg  = idx & 3;
        const __nv_bfloat16* g = (tile == 0) ? Ah : (tile == 1) ? Al : (tile == 2) ? Bh : Bl;
        int grow = ((tile < 2) ? m0 : n0) + row;
        const char* src = (const char*)(g + (size_t)grow * K + k0) + cseg * 16;
        cpasync16(sd + tile * TILE_B + row * 80 + cseg * 16, src);
    }
}

__global__ __launch_bounds__(256, 1)
void gemm_mma(const __nv_bfloat16* __restrict__ Ah, const __nv_bfloat16* __restrict__ Al,
              const __nv_bfloat16* __restrict__ Bh, const __nv_bfloat16* __restrict__ Bl,
              float* __restrict__ C, int N, int K)
{
    extern __shared__ char dsm[];
    const uint32_t sb = smem_u32(dsm);
    const int tid = threadIdx.x;
    const int w = tid >> 5;
    const int l = tid & 31;
    const int wm = (w >> 2) * 64;
    const int wn = (w & 3) * 32;
    const int m0 = blockIdx.y * 128;
    const int n0 = blockIdx.x * 128;
    const int kiters = K / 32;

    load_stage(sb, 0, Ah, Al, Bh, Bl, m0, n0, K, 0, tid);  CP_COMMIT();
    load_stage(sb, 1, Ah, Al, Bh, Bl, m0, n0, K, 32, tid); CP_COMMIT();

    float acc[16][4];
#pragma unroll
    for (int i = 0; i < 16; i++)
#pragma unroll
        for (int j = 0; j < 4; j++) acc[i][j] = 0.f;

    const int a_row = (l & 15);
    const int a_kof = (l >> 4) * 8;
    const int b_row = (l & 7) + ((l >> 4) & 1) * 8;
    const int b_kof = ((l >> 3) & 1) * 8;

    for (int kt = 0; kt < kiters; kt++) {
        CP_WAIT1();
        __syncthreads();
        const uint32_t st = sb + (kt % 3) * STG_B;
        const uint32_t sAh = st;
        const uint32_t sAl = st + TILE_B;
        const uint32_t sBh = st + 2 * TILE_B;
        const uint32_t sBl = st + 3 * TILE_B;

#pragma unroll
        for (int ks = 0; ks < 2; ks++) {
            const int kbase = ks * 16;
            uint32_t ah[4][4], al[4][4], bh[2][4], bl[2][4];
#pragma unroll
            for (int mi = 0; mi < 4; mi++) {
                uint32_t off = (uint32_t)((wm + mi * 16 + a_row) * 80 + (kbase + a_kof) * 2);
                ldmx4(ah[mi], sAh + off);
                ldmx4(al[mi], sAl + off);
            }
#pragma unroll
            for (int ni2 = 0; ni2 < 2; ni2++) {
                uint32_t off = (uint32_t)((wn + ni2 * 16 + b_row) * 80 + (kbase + b_kof) * 2);
                ldmx4(bh[ni2], sBh + off);
                ldmx4(bl[ni2], sBl + off);
            }
#pragma unroll
            for (int mi = 0; mi < 4; mi++) {
#pragma unroll
                for (int ni = 0; ni < 4; ni++) {
                    const uint32_t* bhp = &bh[ni >> 1][(ni & 1) * 2];
                    const uint32_t* blp = &bl[ni >> 1][(ni & 1) * 2];
                    mma16816(acc[mi * 4 + ni], ah[mi], bhp);
                    mma16816(acc[mi * 4 + ni], al[mi], bhp);
                    mma16816(acc[mi * 4 + ni], ah[mi], blp);
                }
            }
        }
        __syncthreads();
        if (kt + 2 < kiters)
            load_stage(sb, (kt + 2) % 3, Ah, Al, Bh, Bl, m0, n0, K, (kt + 2) * 32, tid);
        CP_COMMIT();
    }

#pragma unroll
    for (int mi = 0; mi < 4; mi++) {
#pragma unroll
        for (int ni = 0; ni < 4; ni++) {
            int row = m0 + wm + mi * 16 + (l >> 2);
            int col = n0 + wn + ni * 8 + (l & 3) * 2;
            float* c = C + (size_t)row * N + col;
            float2 v0; v0.x = acc[mi * 4 + ni][0]; v0.y = acc[mi * 4 + ni][1];
            float2 v1; v1.x = acc[mi * 4 + ni][2]; v1.y = acc[mi * 4 + ni][3];
            *(float2*)c = v0;
            *(float2*)(c + 8 * (size_t)N) = v1;
        }
    }
}

// ---------------- RMSNorm + mrope + bf16 hi/lo split ------------------------
// Reads from fused QKV output g_qkv: [tok, 4096] = [q(2048) | k(1024) | v(1024)]
__device__ __forceinline__ int mrope_axis(int d) {
    return d < 21 ? 0 : d < 42 ? 1 : d < 64 ? 2 : d < 85 ? 0 : d < 106 ? 1 : 2;
}

__global__ __launch_bounds__(256)
void norm_rope_kernel(const float* __restrict__ cosb, const float* __restrict__ sinb,
                      const float* __restrict__ qw,   const float* __restrict__ kw)
{
    const int m = blockIdx.x;
    const int b = m >> 11;
    const int s = m & (S_ - 1);
    const int warp = threadIdx.x >> 5;
    const int lane = threadIdx.x & 31;
    const float SC = 0.08838834764831845f;  // 128^-0.5 folded into Q
    const float* tok = g_qkv + (size_t)m * NQKV;

#pragma unroll
    for (int it = 0; it < 4; it++) {
        int slot = warp + (it << 3);
        const float* src; __nv_bfloat16 *dh, *dl; const float* w; bool rope; float scale;
        if (slot < 16) {
            src = tok + slot * D_;
            size_t o = ((size_t)(b * H_ + slot) * S_ + s) * D_;
            dh = g_qh + o; dl = g_ql + o;
            w = qw; rope = true; scale = SC;
        } else if (slot < 24) {
            int hh = slot - 16;
            src = tok + 2048 + hh * D_;
            size_t o = ((size_t)(b * KV_ + hh) * S_ + s) * D_;
            dh = g_kh + o; dl = g_kl + o;
            w = kw; rope = true; scale = 1.f;
        } else {
            int hh = slot - 24;
            src = tok + 3072 + hh * D_;
            size_t o = ((size_t)(b * KV_ + hh) * S_ + s) * D_;
            dh = g_vh + o; dl = g_vl + o;
            w = nullptr; rope = false; scale = 1.f;
        }
        float4 x4 = *(const float4*)(src + lane * 4);
        float out[4] = {x4.x, x4.y, x4.z, x4.w};
        if (rope) {
            float x[4] = {out[0], out[1], out[2], out[3]};
            float ssum = x[0]*x[0] + x[1]*x[1] + x[2]*x[2] + x[3]*x[3];
#pragma unroll
            for (int o2 = 16; o2 > 0; o2 >>= 1)
                ssum += __shfl_xor_sync(0xffffffffu, ssum, o2);
            float r = rsqrtf(ssum * (1.0f / 128.0f) + 1e-6f);
            float4 w4 = *(const float4*)(w + lane * 4);
            float xn[4];
            xn[0] = x[0] * r * w4.x; xn[1] = x[1] * r * w4.y;
            xn[2] = x[2] * r * w4.z; xn[3] = x[3] * r * w4.w;
            float oth[4];
#pragma unroll
            for (int j = 0; j < 4; j++)
                oth[j] = __shfl_xor_sync(0xffffffffu, xn[j], 16);
            float sgn = (lane < 16) ? -1.f : 1.f;
            int dbase = lane * 4;
#pragma unroll
            for (int j = 0; j < 4; j++) {
                int d = dbase + j;
                int ax = mrope_axis(d);
                size_t ci = ((size_t)(ax * B_ + b) * S_ + s) * D_ + d;
                out[j] = (xn[j] * cosb[ci] + sgn * oth[j] * sinb[ci]) * scale;
            }
        }
        __nv_bfloat16 h[4], lo[4];
#pragma unroll
        for (int j = 0; j < 4; j++) {
            h[j]  = __float2bfloat16_rn(out[j]);
            lo[j] = __float2bfloat16_rn(out[j] - __bfloat162float(h[j]));
        }
        __nv_bfloat162* ph = (__nv_bfloat162*)(dh + lane * 4);
        __nv_bfloat162* pl = (__nv_bfloat162*)(dl + lane * 4);
        __nv_bfloat162 t;
        t.x = h[0];  t.y = h[1];  ph[0] = t;
        t.x = h[2];  t.y = h[3];  ph[1] = t;
        t.x = lo[0]; t.y = lo[1]; pl[0] = t;
        t.x = lo[2]; t.y = lo[3]; pl[1] = t;
    }
}

// ---------------- causal GQA flash attention (mma.sync bf16x3) --------------
// CTA: 64 q rows, 128 threads. K-tile 64. D=128. K/V double-buffered.
// qt REVERSED across blockIdx.x: longest CTAs scheduled first.
#define FSTR 136
#define PSTR 72
#define TILE_E (64*FSTR)
#define FLASH_SMEM ((10*TILE_E + 2*64*PSTR)*2)
#define MASKV (-30000.0f)

__device__ __forceinline__ void load_kv_stage(
    __nv_bfloat16* fsb, int st, int k0,
    const __nv_bfloat16* Kh, const __nv_bfloat16* Kl,
    const __nv_bfloat16* Vh, const __nv_bfloat16* Vl, int tid)
{
    __nv_bfloat16* kh = fsb + (2 + st*4) * TILE_E;
    __nv_bfloat16* kl = kh + TILE_E;
    __nv_bfloat16* vh = kl + TILE_E;
    __nv_bfloat16* vl = vh + TILE_E;
#pragma unroll
    for (int i = 0; i < 8; i++) {
        int c = tid + i * 128;
        int r = c >> 4, cs = c & 15;
        size_t go = (size_t)(k0 + r) * D_ + cs * 8;
        uint32_t so = (uint32_t)(r * FSTR + cs * 8);
        cpasync16(smem_u32(kh + so), Kh + go);
        cpasync16(smem_u32(kl + so), Kl + go);
        cpasync16(smem_u32(vh + so), Vh + go);
        cpasync16(smem_u32(vl + so), Vl + go);
    }
}

__global__ __launch_bounds__(128, 1)
void flash_mma(__nv_bfloat16* __restrict__ Oh, __nv_bfloat16* __restrict__ Ol)
{
    extern __shared__ __nv_bfloat16 fsb[];
    __nv_bfloat16* sQh = fsb;
    __nv_bfloat16* sQl = fsb + TILE_E;
    __nv_bfloat16* sPh = fsb + 10 * TILE_E;
    __nv_bfloat16* sPl = sPh + 64 * PSTR;

    const int qt = (int)gridDim.x - 1 - (int)blockIdx.x;  // longest-first
    const int h = blockIdx.y, b = blockIdx.z;
    const int tid = threadIdx.x;
    const int w = tid >> 5;
    const int l = tid & 31;
    const int q0 = qt * 64;

    const __nv_bfloat16* Qbh = g_qh + ((size_t)(b * H_ + h) * S_ + q0) * D_;
    const __nv_bfloat16* Qbl = g_ql + ((size_t)(b * H_ + h) * S_ + q0) * D_;
    const __nv_bfloat16* Kbh = g_kh + (size_t)(b * KV_ + (h >> 1)) * S_ * D_;
    const __nv_bfloat16* Kbl = g_kl + (size_t)(b * KV_ + (h >> 1)) * S_ * D_;
    const __nv_bfloat16* Vbh = g_vh + (size_t)(b * KV_ + (h >> 1)) * S_ * D_;
    const __nv_bfloat16* Vbl = g_vl + (size_t)(b * KV_ + (h >> 1)) * S_ * D_;

    // prologue: Q (64 rows x 16 segs) + KV(tile 0)
#pragma unroll
    for (int i = 0; i < 8; i++) {
        int c = tid + i * 128;
        int r = c >> 4, cs = c & 15;
        size_t go = (size_t)r * D_ + cs * 8;
        uint32_t so = (uint32_t)(r * FSTR + cs * 8);
        cpasync16(smem_u32(sQh + so), Qbh + go);
        cpasync16(smem_u32(sQl + so), Qbl + go);
    }
    load_kv_stage(fsb, 0, 0, Kbh, Kbl, Vbh, Vbl, tid);
    CP_COMMIT();

    float o[16][4];
#pragma unroll
    for (int i = 0; i < 16; i++)
#pragma unroll
        for (int j = 0; j < 4; j++) o[i][j] = 0.f;
    float mrow[2] = {MASKV, MASKV};
    float lrow[2] = {0.f, 0.f};

    const int r0 = l >> 2;
    const int a_row = (l & 15);
    const int a_kof = (l >> 4) * 8;
    const int b_row = (l & 7) + ((l >> 4) & 1) * 8;
    const int b_kof = ((l >> 3) & 1) * 8;
    const int v_row = (l & 15);
    const int v_cof = (l >> 4) * 8;

    for (int t = 0; t <= qt; t++) {
        const int k0 = t * 64;
        const int st = t & 1;
        if (t < qt) {
            load_kv_stage(fsb, st ^ 1, (t + 1) * 64, Kbh, Kbl, Vbh, Vbl, tid);
            CP_COMMIT();
            CP_WAIT1();
        } else {
            CP_WAIT0();
        }
        __syncthreads();

        __nv_bfloat16* sKh = fsb + (2 + st*4) * TILE_E;
        __nv_bfloat16* sKl = sKh + TILE_E;
        __nv_bfloat16* sVh = sKl + TILE_E;
        __nv_bfloat16* sVl = sVh + TILE_E;

        // ---- S = Q K^T ----
        float s[8][4];
#pragma unroll
        for (int i = 0; i < 8; i++)
#pragma unroll
            for (int j = 0; j < 4; j++) s[i][j] = 0.f;

#pragma unroll
        for (int ks = 0; ks < 8; ks++) {
            uint32_t aoff = (uint32_t)((16 * w + a_row) * FSTR + ks * 16 + a_kof) * 2;
            uint32_t ah[4], al[4];
            ldmx4(ah, smem_u32(sQh) + aoff);
            ldmx4(al, smem_u32(sQl) + aoff);
#pragma unroll
            for (int ng = 0; ng < 4; ng++) {
                uint32_t boff = (uint32_t)((16 * ng + b_row) * FSTR + ks * 16 + b_kof) * 2;
                uint32_t bh[4], bl[4];
                ldmx4(bh, smem_u32(sKh) + boff);
                ldmx4(bl, smem_u32(sKl) + boff);
                mma16816(s[2*ng],   ah, &bh[0]);
                mma16816(s[2*ng],   al, &bh[0]);
                mma16816(s[2*ng],   ah, &bl[0]);
                mma16816(s[2*ng+1], ah, &bh[2]);
                mma16816(s[2*ng+1], al, &bh[2]);
                mma16816(s[2*ng+1], ah, &bl[2]);
            }
        }

        // ---- causal mask (diagonal tile only) ----
        if (t == qt) {
            int grow0 = q0 + 16 * w + r0;
            int grow1 = grow0 + 8;
#pragma unroll
            for (int nt = 0; nt < 8; nt++) {
                int col = k0 + nt * 8 + (l & 3) * 2;
                if (col > grow0)     s[nt][0] = MASKV;
                if (col + 1 > grow0) s[nt][1] = MASKV;
                if (col > grow1)     s[nt][2] = MASKV;
                if (col + 1 > grow1) s[nt][3] = MASKV;
            }
        }

        // ---- online softmax (range-safe) ----
        float rm0 = MASKV, rm1 = MASKV;
#pragma unroll
        for (int nt = 0; nt < 8; nt++) {
            rm0 = fmaxf(rm0, fmaxf(s[nt][0], s[nt][1]));
            rm1 = fmaxf(rm1, fmaxf(s[nt][2], s[nt][3]));
        }
        rm0 = fmaxf(rm0, __shfl_xor_sync(0xffffffffu, rm0, 1));
        rm0 = fmaxf(rm0, __shfl_xor_sync(0xffffffffu, rm0, 2));
        rm1 = fmaxf(rm1, __shfl_xor_sync(0xffffffffu, rm1, 1));
        rm1 = fmaxf(rm1, __shfl_xor_sync(0xffffffffu, rm1, 2));

        float mn0 = fmaxf(mrow[0], rm0);
        float mn1 = fmaxf(mrow[1], rm1);
        float alpha0 = fexp(mrow[0] - mn0);
        float alpha1 = fexp(mrow[1] - mn1);
        mrow[0] = mn0; mrow[1] = mn1;

        float rs0 = 0.f, rs1 = 0.f;
#pragma unroll
        for (int nt = 0; nt < 8; nt++) {
            s[nt][0] = fexp(s[nt][0] - mn0);
            s[nt][1] = fexp(s[nt][1] - mn0);
            s[nt][2] = fexp(s[nt][2] - mn1);
            s[nt][3] = fexp(s[nt][3] - mn1);
            rs0 += s[nt][0] + s[nt][1];
            rs1 += s[nt][2] + s[nt][3];
        }
        rs0 += __shfl_xor_sync(0xffffffffu, rs0, 1);
        rs0 += __shfl_xor_sync(0xffffffffu, rs0, 2);
        rs1 += __shfl_xor_sync(0xffffffffu, rs1, 1);
        rs1 += __shfl_xor_sync(0xffffffffu, rs1, 2);
        lrow[0] = lrow[0] * alpha0 + rs0;
        lrow[1] = lrow[1] * alpha1 + rs1;

#pragma unroll
        for (int nt = 0; nt < 16; nt++) {
            o[nt][0] *= alpha0; o[nt][1] *= alpha0;
            o[nt][2] *= alpha1; o[nt][3] *= alpha1;
        }

        // ---- store P (bf16 hi/lo) C-fragment layout, per-warp private rows ----
        {
            int prow0 = 16 * w + r0;
#pragma unroll
            for (int nt = 0; nt < 8; nt++) {
                int pcol = nt * 8 + (l & 3) * 2;
                uint32_t ph0 = packbf(s[nt][0], s[nt][1]);
                __nv_bfloat162 th0 = *(__nv_bfloat162*)&ph0;
                uint32_t pl0 = packbf(s[nt][0] - __bfloat162float(th0.x),
                                      s[nt][1] - __bfloat162float(th0.y));
                *(uint32_t*)(sPh + prow0 * PSTR + pcol) = ph0;
                *(uint32_t*)(sPl + prow0 * PSTR + pcol) = pl0;
                uint32_t ph1 = packbf(s[nt][2], s[nt][3]);
                __nv_bfloat162 th1 = *(__nv_bfloat162*)&ph1;
                uint32_t pl1 = packbf(s[nt][2] - __bfloat162float(th1.x),
                                      s[nt][3] - __bfloat162float(th1.y));
                *(uint32_t*)(sPh + (prow0 + 8) * PSTR + pcol) = ph1;
                *(uint32_t*)(sPl + (prow0 + 8) * PSTR + pcol) = pl1;
            }
        }
        __syncwarp();

        // ---- O += P V ----
#pragma unroll
        for (int ks = 0; ks < 4; ks++) {
            uint32_t poff = (uint32_t)((16 * w + a_row) * PSTR + ks * 16 + a_kof) * 2;
            uint32_t pah[4], pal[4];
            ldmx4(pah, smem_u32(sPh) + poff);
            ldmx4(pal, smem_u32(sPl) + poff);
#pragma unroll
            for (int dg = 0; dg < 8; dg++) {
                uint32_t voff = (uint32_t)((ks * 16 + v_row) * FSTR + dg * 16 + v_cof) * 2;
                uint32_t vh[4], vl[4];
                ldmx4t(vh, smem_u32(sVh) + voff);
                ldmx4t(vl, smem_u32(sVl) + voff);
                mma16816(o[2*dg],   pah, &vh[0]);
                mma16816(o[2*dg],   pal, &vh[0]);
                mma16816(o[2*dg],   pah, &vl[0]);
                mma16816(o[2*dg+1], pah, &vh[2]);
                mma16816(o[2*dg+1], pal, &vh[2]);
                mma16816(o[2*dg+1], pah, &vl[2]);
            }
        }
        __syncthreads();
    }

    // ---- epilogue ----
    float inv0 = 1.f / lrow[0];
    float inv1 = 1.f / lrow[1];
    size_t row0 = (size_t)b * S_ + q0 + 16 * w + r0;
    size_t row1 = row0 + 8;
    int colb = h * D_ + (l & 3) * 2;
#pragma unroll
    for (int nt = 0; nt < 16; nt++) {
        int col = colb + nt * 8;
        float v0 = o[nt][0] * inv0, v1 = o[nt][1] * inv0;
        float v2 = o[nt][2] * inv1, v3 = o[nt][3] * inv1;
        uint32_t h0 = packbf(v0, v1);
        __nv_bfloat162 th = *(__nv_bfloat162*)&h0;
        uint32_t lo0 = packbf(v0 - __bfloat162float(th.x), v1 - __bfloat162float(th.y));
        *(uint32_t*)(Oh + row0 * (H_*D_) + col) = h0;
        *(uint32_t*)(Ol + row0 * (H_*D_) + col) = lo0;
        uint32_t h1 = packbf(v2, v3);
        __nv_bfloat162 th1 = *(__nv_bfloat162*)&h1;
        uint32_t lo1 = packbf(v2 - __bfloat162float(th1.x), v3 - __bfloat162float(th1.y));
        *(uint32_t*)(Oh + row1 * (H_*D_) + col) = h1;
        *(uint32_t*)(Ol + row1 * (H_*D_) + col) = lo1;
    }
}

// ---------------- launcher ---------------------------------------------------
static void launch_split(const float* src, __nv_bfloat16* hi, __nv_bfloat16* lo, int n)
{
    int n4 = n / 4;
    split_bf16_kernel<<<(n4 + 255) / 256, 256>>>(src, hi, lo, n4);
}

extern "C" void kernel_launch(void* const* d_in, const int* in_sizes, int n_in,
                              void* d_out, int out_size)
{
    const float* hidden   = (const float*)d_in[0];
    const float* cosb     = (const float*)d_in[1];
    const float* sinb     = (const float*)d_in[2];
    const float* q_w      = (const float*)d_in[3];
    const float* k_w      = (const float*)d_in[4];
    const float* v_w      = (const float*)d_in[5];
    const float* o_w      = (const float*)d_in[6];
    const float* q_norm_w = (const float*)d_in[7];
    const float* k_norm_w = (const float*)d_in[8];
    float* out = (float*)d_out;

    float* pqkv;
    cudaGetSymbolAddress((void**)&pqkv, g_qkv);

    __nv_bfloat16 *hidh, *hidl, *wh, *wl, *owh, *owl, *ath, *atl;
    cudaGetSymbolAddress((void**)&hidh, g_hid_h); cudaGetSymbolAddress((void**)&hidl, g_hid_l);
    cudaGetSymbolAddress((void**)&wh,   g_w_h);   cudaGetSymbolAddress((void**)&wl,   g_w_l);
    cudaGetSymbolAddress((void**)&owh,  g_ow_h);  cudaGetSymbolAddress((void**)&owl,  g_ow_l);
    cudaGetSymbolAddress((void**)&ath,  g_at_h);  cudaGetSymbolAddress((void**)&atl,  g_at_l);

    cudaFuncSetAttribute(gemm_mma,  cudaFuncAttributeMaxDynamicSharedMemorySize, GEMM_SMEM);
    cudaFuncSetAttribute(flash_mma, cudaFuncAttributeMaxDynamicSharedMemorySize, FLASH_SMEM);

    // 1) split fp32 inputs into bf16 hi/lo (weights into one concat buffer)
    launch_split(hidden, hidh, hidl, MTOK * HID_);
    launch_split(q_w, wh,                 wl,                 H_*D_*HID_);
    launch_split(k_w, wh + (size_t)2048*HID_, wl + (size_t)2048*HID_, KV_*D_*HID_);
    launch_split(v_w, wh + (size_t)3072*HID_, wl + (size_t)3072*HID_, KV_*D_*HID_);
    launch_split(o_w, owh, owl, HID_*H_*D_);

    // 2) fused QKV projection (one launch, N=4096)
    gemm_mma<<<dim3(NQKV/128, MTOK/128), 256, GEMM_SMEM>>>(hidh, hidl, wh, wl, pqkv, NQKV, HID_);

    // 3) RMSNorm + mrope + split to bf16 hi/lo (Q pre-scaled by 1/sqrt(D))
    norm_rope_kernel<<<MTOK, 256>>>(cosb, sinb, q_norm_w, k_norm_w);

    // 4) causal GQA flash attention (longest-first scheduling)
    flash_mma<<<dim3(S_ / 64, H_, B_), 128, FLASH_SMEM>>>(ath, atl);

    // 5) O-projection -> d_out
    gemm_mma<<<dim3(HID_/128, MTOK/128), 256, GEMM_SMEM>>>(ath, atl, owh, owl, out, HID_, H_*D_);
}

// round 8
// speedup vs baseline: 2.7999x; 1.0267x over previous
#include <cuda_runtime.h>
#include <cuda_bf16.h>
#include <math.h>
#include <stdint.h>

// Problem constants
#define B_   2
#define S_   2048
#define HID_ 2048
#define H_   16
#define KV_  8
#define D_   128
#define MTOK (B_*S_)   // 4096 tokens
#define NQKV 4096      // H*D + KV*D + KV*D

// ---------------- scratch (device globals) ----------------------------------
__device__ float g_qkv[MTOK * NQKV];   // fused QKV projection output

__device__ __nv_bfloat16 g_hid_h[MTOK*HID_],  g_hid_l[MTOK*HID_];
__device__ __nv_bfloat16 g_w_h [NQKV*HID_],   g_w_l [NQKV*HID_];   // q|k|v weights concat
__device__ __nv_bfloat16 g_ow_h[HID_*H_*D_],  g_ow_l[HID_*H_*D_];

// roped/normed operands for flash (bf16 hi/lo), [B,H|KV,S,D]
__device__ __nv_bfloat16 g_qh[B_*H_*S_*D_],  g_ql[B_*H_*S_*D_];
__device__ __nv_bfloat16 g_kh[B_*KV_*S_*D_], g_kl[B_*KV_*S_*D_];
__device__ __nv_bfloat16 g_vh[B_*KV_*S_*D_], g_vl[B_*KV_*S_*D_];
// attention output (bf16 hi/lo), [B*S, H*D]
__device__ __nv_bfloat16 g_at_h[MTOK*H_*D_], g_at_l[MTOK*H_*D_];

// ======================= PTX helpers (sm_80-era) ===========================
__device__ __forceinline__ uint32_t smem_u32(const void* p) {
    return (uint32_t)__cvta_generic_to_shared(p);
}
__device__ __forceinline__ void cpasync16(uint32_t dst, const void* src) {
    asm volatile("cp.async.cg.shared.global [%0], [%1], 16;" :: "r"(dst), "l"(src));
}
#define CP_COMMIT() asm volatile("cp.async.commit_group;" ::: "memory")
#define CP_WAIT1()  asm volatile("cp.async.wait_group 1;" ::: "memory")
#define CP_WAIT0()  asm volatile("cp.async.wait_group 0;" ::: "memory")

__device__ __forceinline__ void ldmx4(uint32_t* r, uint32_t addr) {
    asm volatile("ldmatrix.sync.aligned.m8n8.x4.shared.b16 {%0,%1,%2,%3}, [%4];"
                 : "=r"(r[0]), "=r"(r[1]), "=r"(r[2]), "=r"(r[3]) : "r"(addr));
}
__device__ __forceinline__ void ldmx4t(uint32_t* r, uint32_t addr) {
    asm volatile("ldmatrix.sync.aligned.m8n8.x4.trans.shared.b16 {%0,%1,%2,%3}, [%4];"
                 : "=r"(r[0]), "=r"(r[1]), "=r"(r[2]), "=r"(r[3]) : "r"(addr));
}
__device__ __forceinline__ void mma16816(float* d, const uint32_t* a, const uint32_t* b) {
    asm volatile("mma.sync.aligned.m16n8k16.row.col.f32.bf16.bf16.f32 "
                 "{%0,%1,%2,%3}, {%4,%5,%6,%7}, {%8,%9}, {%0,%1,%2,%3};"
                 : "+f"(d[0]), "+f"(d[1]), "+f"(d[2]), "+f"(d[3])
                 : "r"(a[0]), "r"(a[1]), "r"(a[2]), "r"(a[3]), "r"(b[0]), "r"(b[1]));
}
__device__ __forceinline__ uint32_t packbf(float x, float y) {
    __nv_bfloat162 t;
    t.x = __float2bfloat16_rn(x); t.y = __float2bfloat16_rn(y);
    return *(uint32_t*)&t;
}
__device__ __forceinline__ float fexp(float x) {
    return __expf(fmaxf(x, -80.0f));   // range-safe exp
}

// ======================= fp32 -> bf16 hi/lo split ==========================
__global__ __launch_bounds__(256)
void split_bf16_kernel(const float* __restrict__ src,
                       __nv_bfloat16* __restrict__ hi,
                       __nv_bfloat16* __restrict__ lo, int n4)
{
    int i = blockIdx.x * blockDim.x + threadIdx.x;
    if (i >= n4) return;
    float4 x = ((const float4*)src)[i];
    float xs[4] = {x.x, x.y, x.z, x.w};
    __nv_bfloat16 h[4], l[4];
#pragma unroll
    for (int j = 0; j < 4; j++) {
        h[j] = __float2bfloat16_rn(xs[j]);
        l[j] = __float2bfloat16_rn(xs[j] - __bfloat162float(h[j]));
    }
    __nv_bfloat162 h0; h0.x = h[0]; h0.y = h[1];
    __nv_bfloat162 h1; h1.x = h[2]; h1.y = h[3];
    __nv_bfloat162 l0; l0.x = l[0]; l0.y = l[1];
    __nv_bfloat162 l1; l1.x = l[2]; l1.y = l[3];
    ((__nv_bfloat162*)hi)[i*2 + 0] = h0;
    ((__nv_bfloat162*)hi)[i*2 + 1] = h1;
    ((__nv_bfloat162*)lo)[i*2 + 0] = l0;
    ((__nv_bfloat162*)lo)[i*2 + 1] = l1;
}

// ======================= mma.sync bf16x3 GEMM (NT) =========================
#define LDT   40
#define TILE_B (128*LDT*2)
#define STG_B  (4*TILE_B)
#define NSTG  3
#define GEMM_SMEM (NSTG*STG_B)

__device__ __forceinline__ void load_stage(
    uint32_t sbase, int stg,
    const __nv_bfloat16* __restrict__ Ah, const __nv_bfloat16* __restrict__ Al,
    const __nv_bfloat16* __restrict__ Bh, const __nv_bfloat16* __restrict__ Bl,
    int m0, int n0, int K, int k0, int tid)
{
    uint32_t sd = sbase + stg * STG_B;
#pragma unroll
    for (int i = 0; i < 8; i++) {
        int chunk = i * 256 + tid;
        int tile  = chunk >> 9;
        int idx   = chunk & 511;
        int row   = idx >> 2;
        int cseg  = idx & 3;
        const __nv_bfloat16* g = (tile == 0) ? Ah : (tile == 1) ? Al : (tile == 2) ? Bh : Bl;
        int grow = ((tile < 2) ? m0 : n0) + row;
        const char* src = (const char*)(g + (size_t)grow * K + k0) + cseg * 16;
        cpasync16(sd + tile * TILE_B + row * 80 + cseg * 16, src);
    }
}

__global__ __launch_bounds__(256, 1)
void gemm_mma(const __nv_bfloat16* __restrict__ Ah, const __nv_bfloat16* __restrict__ Al,
              const __nv_bfloat16* __restrict__ Bh, const __nv_bfloat16* __restrict__ Bl,
              float* __restrict__ C, int N, int K)
{
    extern __shared__ char dsm[];
    const uint32_t sb = smem_u32(dsm);
    const int tid = threadIdx.x;
    const int w = tid >> 5;
    const int l = tid & 31;
    const int wm = (w >> 2) * 64;
    const int wn = (w & 3) * 32;
    const int m0 = blockIdx.y * 128;
    const int n0 = blockIdx.x * 128;
    const int kiters = K / 32;

    load_stage(sb, 0, Ah, Al, Bh, Bl, m0, n0, K, 0, tid);  CP_COMMIT();
    load_stage(sb, 1, Ah, Al, Bh, Bl, m0, n0, K, 32, tid); CP_COMMIT();

    float acc[16][4];
#pragma unroll
    for (int i = 0; i < 16; i++)
#pragma unroll
        for (int j = 0; j < 4; j++) acc[i][j] = 0.f;

    const int a_row = (l & 15);
    const int a_kof = (l >> 4) * 8;
    const int b_row = (l & 7) + ((l >> 4) & 1) * 8;
    const int b_kof = ((l >> 3) & 1) * 8;

    for (int kt = 0; kt < kiters; kt++) {
        CP_WAIT1();
        __syncthreads();
        const uint32_t st = sb + (kt % 3) * STG_B;
        const uint32_t sAh = st;
        const uint32_t sAl = st + TILE_B;
        const uint32_t sBh = st + 2 * TILE_B;
        const uint32_t sBl = st + 3 * TILE_B;

#pragma unroll
        for (int ks = 0; ks < 2; ks++) {
            const int kbase = ks * 16;
            uint32_t ah[4][4], al[4][4], bh[2][4], bl[2][4];
#pragma unroll
            for (int mi = 0; mi < 4; mi++) {
                uint32_t off = (uint32_t)((wm + mi * 16 + a_row) * 80 + (kbase + a_kof) * 2);
                ldmx4(ah[mi], sAh + off);
                ldmx4(al[mi], sAl + off);
            }
#pragma unroll
            for (int ni2 = 0; ni2 < 2; ni2++) {
                uint32_t off = (uint32_t)((wn + ni2 * 16 + b_row) * 80 + (kbase + b_kof) * 2);
                ldmx4(bh[ni2], sBh + off);
                ldmx4(bl[ni2], sBl + off);
            }
#pragma unroll
            for (int mi = 0; mi < 4; mi++) {
#pragma unroll
                for (int ni = 0; ni < 4; ni++) {
                    const uint32_t* bhp = &bh[ni >> 1][(ni & 1) * 2];
                    const uint32_t* blp = &bl[ni >> 1][(ni & 1) * 2];
                    mma16816(acc[mi * 4 + ni], ah[mi], bhp);
                    mma16816(acc[mi * 4 + ni], al[mi], bhp);
                    mma16816(acc[mi * 4 + ni], ah[mi], blp);
                }
            }
        }
        __syncthreads();
        if (kt + 2 < kiters)
            load_stage(sb, (kt + 2) % 3, Ah, Al, Bh, Bl, m0, n0, K, (kt + 2) * 32, tid);
        CP_COMMIT();
    }

#pragma unroll
    for (int mi = 0; mi < 4; mi++) {
#pragma unroll
        for (int ni = 0; ni < 4; ni++) {
            int row = m0 + wm + mi * 16 + (l >> 2);
            int col = n0 + wn + ni * 8 + (l & 3) * 2;
            float* c = C + (size_t)row * N + col;
            float2 v0; v0.x = acc[mi * 4 + ni][0]; v0.y = acc[mi * 4 + ni][1];
            float2 v1; v1.x = acc[mi * 4 + ni][2]; v1.y = acc[mi * 4 + ni][3];
            *(float2*)c = v0;
            *(float2*)(c + 8 * (size_t)N) = v1;
        }
    }
}

// ---------------- RMSNorm + mrope + bf16 hi/lo split ------------------------
__device__ __forceinline__ int mrope_axis(int d) {
    return d < 21 ? 0 : d < 42 ? 1 : d < 64 ? 2 : d < 85 ? 0 : d < 106 ? 1 : 2;
}

__global__ __launch_bounds__(256)
void norm_rope_kernel(const float* __restrict__ cosb, const float* __restrict__ sinb,
                      const float* __restrict__ qw,   const float* __restrict__ kw)
{
    const int m = blockIdx.x;
    const int b = m >> 11;
    const int s = m & (S_ - 1);
    const int warp = threadIdx.x >> 5;
    const int lane = threadIdx.x & 31;
    const float SC = 0.08838834764831845f;
    const float* tok = g_qkv + (size_t)m * NQKV;

#pragma unroll
    for (int it = 0; it < 4; it++) {
        int slot = warp + (it << 3);
        const float* src; __nv_bfloat16 *dh, *dl; const float* w; bool rope; float scale;
        if (slot < 16) {
            src = tok + slot * D_;
            size_t o = ((size_t)(b * H_ + slot) * S_ + s) * D_;
            dh = g_qh + o; dl = g_ql + o;
            w = qw; rope = true; scale = SC;
        } else if (slot < 24) {
            int hh = slot - 16;
            src = tok + 2048 + hh * D_;
            size_t o = ((size_t)(b * KV_ + hh) * S_ + s) * D_;
            dh = g_kh + o; dl = g_kl + o;
            w = kw; rope = true; scale = 1.f;
        } else {
            int hh = slot - 24;
            src = tok + 3072 + hh * D_;
            size_t o = ((size_t)(b * KV_ + hh) * S_ + s) * D_;
            dh = g_vh + o; dl = g_vl + o;
            w = nullptr; rope = false; scale = 1.f;
        }
        float4 x4 = *(const float4*)(src + lane * 4);
        float out[4] = {x4.x, x4.y, x4.z, x4.w};
        if (rope) {
            float x[4] = {out[0], out[1], out[2], out[3]};
            float ssum = x[0]*x[0] + x[1]*x[1] + x[2]*x[2] + x[3]*x[3];
#pragma unroll
            for (int o2 = 16; o2 > 0; o2 >>= 1)
                ssum += __shfl_xor_sync(0xffffffffu, ssum, o2);
            float r = rsqrtf(ssum * (1.0f / 128.0f) + 1e-6f);
            float4 w4 = *(const float4*)(w + lane * 4);
            float xn[4];
            xn[0] = x[0] * r * w4.x; xn[1] = x[1] * r * w4.y;
            xn[2] = x[2] * r * w4.z; xn[3] = x[3] * r * w4.w;
            float oth[4];
#pragma unroll
            for (int j = 0; j < 4; j++)
                oth[j] = __shfl_xor_sync(0xffffffffu, xn[j], 16);
            float sgn = (lane < 16) ? -1.f : 1.f;
            int dbase = lane * 4;
#pragma unroll
            for (int j = 0; j < 4; j++) {
                int d = dbase + j;
                int ax = mrope_axis(d);
                size_t ci = ((size_t)(ax * B_ + b) * S_ + s) * D_ + d;
                out[j] = (xn[j] * cosb[ci] + sgn * oth[j] * sinb[ci]) * scale;
            }
        }
        __nv_bfloat16 h[4], lo[4];
#pragma unroll
        for (int j = 0; j < 4; j++) {
            h[j]  = __float2bfloat16_rn(out[j]);
            lo[j] = __float2bfloat16_rn(out[j] - __bfloat162float(h[j]));
        }
        __nv_bfloat162* ph = (__nv_bfloat162*)(dh + lane * 4);
        __nv_bfloat162* pl = (__nv_bfloat162*)(dl + lane * 4);
        __nv_bfloat162 t;
        t.x = h[0];  t.y = h[1];  ph[0] = t;
        t.x = h[2];  t.y = h[3];  ph[1] = t;
        t.x = lo[0]; t.y = lo[1]; pl[0] = t;
        t.x = lo[2]; t.y = lo[3]; pl[1] = t;
    }
}

// ---------------- causal GQA flash attention (mma.sync bf16x3) --------------
// CTA: 128 q rows, 256 threads (8 warps x 16 rows). K-tile 64, double-buffered.
// P kept in registers (C-fragment == A-fragment permutation for m16n8k16).
#define FSTR 136
#define QTILE_E (128*FSTR)       // Q tile elems (hi or lo)
#define KTILE_E (64*FSTR)        // K/V tile elems
#define FLASH_SMEM ((2*QTILE_E + 8*KTILE_E)*2)   // 208896 bytes
#define MASKV (-30000.0f)

__device__ __forceinline__ void load_kv_stage(
    __nv_bfloat16* fsb, int st, int k0,
    const __nv_bfloat16* Kh, const __nv_bfloat16* Kl,
    const __nv_bfloat16* Vh, const __nv_bfloat16* Vl, int tid)
{
    __nv_bfloat16* kh = fsb + 2*QTILE_E + st * 4 * KTILE_E;
    __nv_bfloat16* kl = kh + KTILE_E;
    __nv_bfloat16* vh = kl + KTILE_E;
    __nv_bfloat16* vl = vh + KTILE_E;
    // 64 rows x 16 segs = 1024 chunks per array; 256 threads -> 4 each
#pragma unroll
    for (int i = 0; i < 4; i++) {
        int c = tid + i * 256;
        int r = c >> 4, cs = c & 15;
        size_t go = (size_t)(k0 + r) * D_ + cs * 8;
        uint32_t so = (uint32_t)(r * FSTR + cs * 8);
        cpasync16(smem_u32(kh + so), Kh + go);
        cpasync16(smem_u32(kl + so), Kl + go);
        cpasync16(smem_u32(vh + so), Vh + go);
        cpasync16(smem_u32(vl + so), Vl + go);
    }
}

__global__ __launch_bounds__(256, 1)
void flash_mma(__nv_bfloat16* __restrict__ Oh, __nv_bfloat16* __restrict__ Ol)
{
    extern __shared__ __nv_bfloat16 fsb[];
    __nv_bfloat16* sQh = fsb;
    __nv_bfloat16* sQl = fsb + QTILE_E;

    const int qt = (int)gridDim.x - 1 - (int)blockIdx.x;  // longest-first
    const int h = blockIdx.y, b = blockIdx.z;
    const int tid = threadIdx.x;
    const int w = tid >> 5;
    const int l = tid & 31;
    const int q0 = qt * 128;

    const __nv_bfloat16* Qbh = g_qh + ((size_t)(b * H_ + h) * S_ + q0) * D_;
    const __nv_bfloat16* Qbl = g_ql + ((size_t)(b * H_ + h) * S_ + q0) * D_;
    const __nv_bfloat16* Kbh = g_kh + (size_t)(b * KV_ + (h >> 1)) * S_ * D_;
    const __nv_bfloat16* Kbl = g_kl + (size_t)(b * KV_ + (h >> 1)) * S_ * D_;
    const __nv_bfloat16* Vbh = g_vh + (size_t)(b * KV_ + (h >> 1)) * S_ * D_;
    const __nv_bfloat16* Vbl = g_vl + (size_t)(b * KV_ + (h >> 1)) * S_ * D_;

    // prologue: Q (128 rows x 16 segs = 2048 chunks per array) + KV(tile 0)
#pragma unroll
    for (int i = 0; i < 8; i++) {
        int c = tid + i * 256;
        int r = c >> 4, cs = c & 15;
        size_t go = (size_t)r * D_ + cs * 8;
        uint32_t so = (uint32_t)(r * FSTR + cs * 8);
        cpasync16(smem_u32(sQh + so), Qbh + go);
        cpasync16(smem_u32(sQl + so), Qbl + go);
    }
    load_kv_stage(fsb, 0, 0, Kbh, Kbl, Vbh, Vbl, tid);
    CP_COMMIT();

    float o[16][4];
#pragma unroll
    for (int i = 0; i < 16; i++)
#pragma unroll
        for (int j = 0; j < 4; j++) o[i][j] = 0.f;
    float mrow[2] = {MASKV, MASKV};
    float lrow[2] = {0.f, 0.f};

    const int r0 = l >> 2;
    const int a_row = (l & 15);
    const int a_kof = (l >> 4) * 8;
    const int b_row = (l & 7) + ((l >> 4) & 1) * 8;
    const int b_kof = ((l >> 3) & 1) * 8;
    const int v_row = (l & 15);
    const int v_cof = (l >> 4) * 8;
    const int wrow_lo = q0 + 16 * w;          // warp's first q row
    const int ntiles = 2 * qt + 2;

    for (int t = 0; t < ntiles; t++) {
        const int k0 = t * 64;
        const int st = t & 1;
        if (t + 1 < ntiles) {
            load_kv_stage(fsb, st ^ 1, (t + 1) * 64, Kbh, Kbl, Vbh, Vbl, tid);
            CP_COMMIT();
            CP_WAIT1();
        } else {
            CP_WAIT0();
        }
        __syncthreads();

        // warp fully above diagonal for this k-tile? skip compute
        if (k0 <= wrow_lo + 15) {
            __nv_bfloat16* sKh = fsb + 2*QTILE_E + st * 4 * KTILE_E;
            __nv_bfloat16* sKl = sKh + KTILE_E;
            __nv_bfloat16* sVh = sKl + KTILE_E;
            __nv_bfloat16* sVl = sVh + KTILE_E;

            // ---- S = Q K^T : warp rows 16w..16w+15, 64 cols ----
            float s[8][4];
#pragma unroll
            for (int i = 0; i < 8; i++)
#pragma unroll
                for (int j = 0; j < 4; j++) s[i][j] = 0.f;

#pragma unroll
            for (int ks = 0; ks < 8; ks++) {
                uint32_t aoff = (uint32_t)((16 * w + a_row) * FSTR + ks * 16 + a_kof) * 2;
                uint32_t ah[4], al[4];
                ldmx4(ah, smem_u32(sQh) + aoff);
                ldmx4(al, smem_u32(sQl) + aoff);
#pragma unroll
                for (int ng = 0; ng < 4; ng++) {
                    uint32_t boff = (uint32_t)((16 * ng + b_row) * FSTR + ks * 16 + b_kof) * 2;
                    uint32_t bh[4], bl[4];
                    ldmx4(bh, smem_u32(sKh) + boff);
                    ldmx4(bl, smem_u32(sKl) + boff);
                    mma16816(s[2*ng],   ah, &bh[0]);
                    mma16816(s[2*ng],   al, &bh[0]);
                    mma16816(s[2*ng],   ah, &bl[0]);
                    mma16816(s[2*ng+1], ah, &bh[2]);
                    mma16816(s[2*ng+1], al, &bh[2]);
                    mma16816(s[2*ng+1], ah, &bl[2]);
                }
            }

            // ---- causal mask (boundary k-tiles only) ----
            if (k0 + 63 > wrow_lo) {
                int grow0 = wrow_lo + r0;
                int grow1 = grow0 + 8;
#pragma unroll
                for (int nt = 0; nt < 8; nt++) {
                    int col = k0 + nt * 8 + (l & 3) * 2;
                    if (col > grow0)     s[nt][0] = MASKV;
                    if (col + 1 > grow0) s[nt][1] = MASKV;
                    if (col > grow1)     s[nt][2] = MASKV;
                    if (col + 1 > grow1) s[nt][3] = MASKV;
                }
            }

            // ---- online softmax (range-safe) ----
            float rm0 = MASKV, rm1 = MASKV;
#pragma unroll
            for (int nt = 0; nt < 8; nt++) {
                rm0 = fmaxf(rm0, fmaxf(s[nt][0], s[nt][1]));
                rm1 = fmaxf(rm1, fmaxf(s[nt][2], s[nt][3]));
            }
            rm0 = fmaxf(rm0, __shfl_xor_sync(0xffffffffu, rm0, 1));
            rm0 = fmaxf(rm0, __shfl_xor_sync(0xffffffffu, rm0, 2));
            rm1 = fmaxf(rm1, __shfl_xor_sync(0xffffffffu, rm1, 1));
            rm1 = fmaxf(rm1, __shfl_xor_sync(0xffffffffu, rm1, 2));

            float mn0 = fmaxf(mrow[0], rm0);
            float mn1 = fmaxf(mrow[1], rm1);
            float alpha0 = fexp(mrow[0] - mn0);
            float alpha1 = fexp(mrow[1] - mn1);
            mrow[0] = mn0; mrow[1] = mn1;

            float rs0 = 0.f, rs1 = 0.f;
#pragma unroll
            for (int nt = 0; nt < 8; nt++) {
                s[nt][0] = fexp(s[nt][0] - mn0);
                s[nt][1] = fexp(s[nt][1] - mn0);
                s[nt][2] = fexp(s[nt][2] - mn1);
                s[nt][3] = fexp(s[nt][3] - mn1);
                rs0 += s[nt][0] + s[nt][1];
                rs1 += s[nt][2] + s[nt][3];
            }
            rs0 += __shfl_xor_sync(0xffffffffu, rs0, 1);
            rs0 += __shfl_xor_sync(0xffffffffu, rs0, 2);
            rs1 += __shfl_xor_sync(0xffffffffu, rs1, 1);
            rs1 += __shfl_xor_sync(0xffffffffu, rs1, 2);
            lrow[0] = lrow[0] * alpha0 + rs0;
            lrow[1] = lrow[1] * alpha1 + rs1;

#pragma unroll
            for (int nt = 0; nt < 16; nt++) {
                o[nt][0] *= alpha0; o[nt][1] *= alpha0;
                o[nt][2] *= alpha1; o[nt][3] *= alpha1;
            }

            // ---- O += P V : P built in registers (C-frag == A-frag perm) ----
#pragma unroll
            for (int ks = 0; ks < 4; ks++) {
                float p00 = s[2*ks][0],   p01 = s[2*ks][1];
                float p02 = s[2*ks][2],   p03 = s[2*ks][3];
                float p10 = s[2*ks+1][0], p11 = s[2*ks+1][1];
                float p12 = s[2*ks+1][2], p13 = s[2*ks+1][3];
                uint32_t pah[4], pal[4];
                pah[0] = packbf(p00, p01);
                pah[1] = packbf(p02, p03);
                pah[2] = packbf(p10, p11);
                pah[3] = packbf(p12, p13);
                __nv_bfloat162 t0 = *(__nv_bfloat162*)&pah[0];
                __nv_bfloat162 t1 = *(__nv_bfloat162*)&pah[1];
                __nv_bfloat162 t2 = *(__nv_bfloat162*)&pah[2];
                __nv_bfloat162 t3 = *(__nv_bfloat162*)&pah[3];
                pal[0] = packbf(p00 - __bfloat162float(t0.x), p01 - __bfloat162float(t0.y));
                pal[1] = packbf(p02 - __bfloat162float(t1.x), p03 - __bfloat162float(t1.y));
                pal[2] = packbf(p10 - __bfloat162float(t2.x), p11 - __bfloat162float(t2.y));
                pal[3] = packbf(p12 - __bfloat162float(t3.x), p13 - __bfloat162float(t3.y));

#pragma unroll
                for (int dg = 0; dg < 8; dg++) {
                    uint32_t voff = (uint32_t)((ks * 16 + v_row) * FSTR + dg * 16 + v_cof) * 2;
                    uint32_t vh[4], vl[4];
                    ldmx4t(vh, smem_u32(sVh) + voff);
                    ldmx4t(vl, smem_u32(sVl) + voff);
                    mma16816(o[2*dg],   pah, &vh[0]);
                    mma16816(o[2*dg],   pal, &vh[0]);
                    mma16816(o[2*dg],   pah, &vl[0]);
                    mma16816(o[2*dg+1], pah, &vh[2]);
                    mma16816(o[2*dg+1], pal, &vh[2]);
                    mma16816(o[2*dg+1], pah, &vl[2]);
                }
            }
        }
        __syncthreads();   // all reads of stage st done before it is refilled
    }

    // ---- epilogue ----
    float inv0 = 1.f / lrow[0];
    float inv1 = 1.f / lrow[1];
    size_t row0 = (size_t)b * S_ + q0 + 16 * w + r0;
    size_t row1 = row0 + 8;
    int colb = h * D_ + (l & 3) * 2;
#pragma unroll
    for (int nt = 0; nt < 16; nt++) {
        int col = colb + nt * 8;
        float v0 = o[nt][0] * inv0, v1 = o[nt][1] * inv0;
        float v2 = o[nt][2] * inv1, v3 = o[nt][3] * inv1;
        uint32_t h0 = packbf(v0, v1);
        __nv_bfloat162 th = *(__nv_bfloat162*)&h0;
        uint32_t lo0 = packbf(v0 - __bfloat162float(th.x), v1 - __bfloat162float(th.y));
        *(uint32_t*)(Oh + row0 * (H_*D_) + col) = h0;
        *(uint32_t*)(Ol + row0 * (H_*D_) + col) = lo0;
        uint32_t h1 = packbf(v2, v3);
        __nv_bfloat162 th1 = *(__nv_bfloat162*)&h1;
        uint32_t lo1 = packbf(v2 - __bfloat162float(th1.x), v3 - __bfloat162float(th1.y));
        *(uint32_t*)(Oh + row1 * (H_*D_) + col) = h1;
        *(uint32_t*)(Ol + row1 * (H_*D_) + col) = lo1;
    }
}

// ---------------- launcher ---------------------------------------------------
static void launch_split(const float* src, __nv_bfloat16* hi, __nv_bfloat16* lo, int n)
{
    int n4 = n / 4;
    split_bf16_kernel<<<(n4 + 255) / 256, 256>>>(src, hi, lo, n4);
}

extern "C" void kernel_launch(void* const* d_in, const int* in_sizes, int n_in,
                              void* d_out, int out_size)
{
    const float* hidden   = (const float*)d_in[0];
    const float* cosb     = (const float*)d_in[1];
    const float* sinb     = (const float*)d_in[2];
    const float* q_w      = (const float*)d_in[3];
    const float* k_w      = (const float*)d_in[4];
    const float* v_w      = (const float*)d_in[5];
    const float* o_w      = (const float*)d_in[6];
    const float* q_norm_w = (const float*)d_in[7];
    const float* k_norm_w = (const float*)d_in[8];
    float* out = (float*)d_out;

    float* pqkv;
    cudaGetSymbolAddress((void**)&pqkv, g_qkv);

    __nv_bfloat16 *hidh, *hidl, *wh, *wl, *owh, *owl, *ath, *atl;
    cudaGetSymbolAddress((void**)&hidh, g_hid_h); cudaGetSymbolAddress((void**)&hidl, g_hid_l);
    cudaGetSymbolAddress((void**)&wh,   g_w_h);   cudaGetSymbolAddress((void**)&wl,   g_w_l);
    cudaGetSymbolAddress((void**)&owh,  g_ow_h);  cudaGetSymbolAddress((void**)&owl,  g_ow_l);
    cudaGetSymbolAddress((void**)&ath,  g_at_h);  cudaGetSymbolAddress((void**)&atl,  g_at_l);

    cudaFuncSetAttribute(gemm_mma,  cudaFuncAttributeMaxDynamicSharedMemorySize, GEMM_SMEM);
    cudaFuncSetAttribute(flash_mma, cudaFuncAttributeMaxDynamicSharedMemorySize, FLASH_SMEM);

    // 1) split fp32 inputs into bf16 hi/lo
    launch_split(hidden, hidh, hidl, MTOK * HID_);
    launch_split(q_w, wh,                 wl,                 H_*D_*HID_);
    launch_split(k_w, wh + (size_t)2048*HID_, wl + (size_t)2048*HID_, KV_*D_*HID_);
    launch_split(v_w, wh + (size_t)3072*HID_, wl + (size_t)3072*HID_, KV_*D_*HID_);
    launch_split(o_w, owh, owl, HID_*H_*D_);

    // 2) fused QKV projection (one launch, N=4096)
    gemm_mma<<<dim3(NQKV/128, MTOK/128), 256, GEMM_SMEM>>>(hidh, hidl, wh, wl, pqkv, NQKV, HID_);

    // 3) RMSNorm + mrope + split to bf16 hi/lo (Q pre-scaled by 1/sqrt(D))
    norm_rope_kernel<<<MTOK, 256>>>(cosb, sinb, q_norm_w, k_norm_w);

    // 4) causal GQA flash attention (128 q-rows/CTA, 8 warps, reg-P)
    flash_mma<<<dim3(S_ / 128, H_, B_), 256, FLASH_SMEM>>>(ath, atl);

    // 5) O-projection -> d_out
    gemm_mma<<<dim3(HID_/128, MTOK/128), 256, GEMM_SMEM>>>(ath, atl, owh, owl, out, HID_, H_*D_);
}

// round 9
// speedup vs baseline: 3.4019x; 1.2150x over previous
#include <cuda_runtime.h>
#include <cuda_bf16.h>
#include <cuda_fp16.h>
#include <math.h>
#include <stdint.h>

// Problem constants
#define B_   2
#define S_   2048
#define HID_ 2048
#define H_   16
#define KV_  8
#define D_   128
#define MTOK (B_*S_)   // 4096 tokens
#define NQKV 4096

// ---------------- scratch (device globals) ----------------------------------
__device__ float g_qkv[MTOK * NQKV];   // fused QKV projection output

__device__ __nv_bfloat16 g_hid_h[MTOK*HID_],  g_hid_l[MTOK*HID_];
__device__ __nv_bfloat16 g_w_h [NQKV*HID_],   g_w_l [NQKV*HID_];   // q|k|v weights concat
__device__ __half        g_ow16[HID_*H_*D_];                        // o_w single fp16

// roped/normed operands for flash (fp16), [B,H|KV,S,D]
__device__ __half g_qh[B_*H_*S_*D_], g_ql[B_*H_*S_*D_];   // Q hi/lo
__device__ __half g_k16[B_*KV_*S_*D_];                    // K single
__device__ __half g_v16[B_*KV_*S_*D_];                    // V single
// attention output (fp16 hi/lo), [B*S, H*D]
__device__ __half g_at_h[MTOK*H_*D_], g_at_l[MTOK*H_*D_];

// ======================= PTX helpers (sm_80-era) ===========================
__device__ __forceinline__ uint32_t smem_u32(const void* p) {
    return (uint32_t)__cvta_generic_to_shared(p);
}
__device__ __forceinline__ void cpasync16(uint32_t dst, const void* src) {
    asm volatile("cp.async.cg.shared.global [%0], [%1], 16;" :: "r"(dst), "l"(src));
}
#define CP_COMMIT() asm volatile("cp.async.commit_group;" ::: "memory")
#define CP_WAIT1()  asm volatile("cp.async.wait_group 1;" ::: "memory")
#define CP_WAIT0()  asm volatile("cp.async.wait_group 0;" ::: "memory")

__device__ __forceinline__ void ldmx4(uint32_t* r, uint32_t addr) {
    asm volatile("ldmatrix.sync.aligned.m8n8.x4.shared.b16 {%0,%1,%2,%3}, [%4];"
                 : "=r"(r[0]), "=r"(r[1]), "=r"(r[2]), "=r"(r[3]) : "r"(addr));
}
__device__ __forceinline__ void ldmx4t(uint32_t* r, uint32_t addr) {
    asm volatile("ldmatrix.sync.aligned.m8n8.x4.trans.shared.b16 {%0,%1,%2,%3}, [%4];"
                 : "=r"(r[0]), "=r"(r[1]), "=r"(r[2]), "=r"(r[3]) : "r"(addr));
}
// bf16 mma
__device__ __forceinline__ void mma16816(float* d, const uint32_t* a, const uint32_t* b) {
    asm volatile("mma.sync.aligned.m16n8k16.row.col.f32.bf16.bf16.f32 "
                 "{%0,%1,%2,%3}, {%4,%5,%6,%7}, {%8,%9}, {%0,%1,%2,%3};"
                 : "+f"(d[0]), "+f"(d[1]), "+f"(d[2]), "+f"(d[3])
                 : "r"(a[0]), "r"(a[1]), "r"(a[2]), "r"(a[3]), "r"(b[0]), "r"(b[1]));
}
// fp16 mma
__device__ __forceinline__ void mma16816h(float* d, const uint32_t* a, const uint32_t* b) {
    asm volatile("mma.sync.aligned.m16n8k16.row.col.f32.f16.f16.f32 "
                 "{%0,%1,%2,%3}, {%4,%5,%6,%7}, {%8,%9}, {%0,%1,%2,%3};"
                 : "+f"(d[0]), "+f"(d[1]), "+f"(d[2]), "+f"(d[3])
                 : "r"(a[0]), "r"(a[1]), "r"(a[2]), "r"(a[3]), "r"(b[0]), "r"(b[1]));
}
__device__ __forceinline__ uint32_t packh(float x, float y) {
    __half2 t; t.x = __float2half_rn(x); t.y = __float2half_rn(y);
    return *(uint32_t*)&t;
}
__device__ __forceinline__ float fexp(float x) {
    return __expf(fmaxf(x, -80.0f));
}

// ======================= fp32 -> bf16 hi/lo split ==========================
__global__ __launch_bounds__(256)
void split_bf16_kernel(const float* __restrict__ src,
                       __nv_bfloat16* __restrict__ hi,
                       __nv_bfloat16* __restrict__ lo, int n4)
{
    int i = blockIdx.x * blockDim.x + threadIdx.x;
    if (i >= n4) return;
    float4 x = ((const float4*)src)[i];
    float xs[4] = {x.x, x.y, x.z, x.w};
    __nv_bfloat16 h[4], l[4];
#pragma unroll
    for (int j = 0; j < 4; j++) {
        h[j] = __float2bfloat16_rn(xs[j]);
        l[j] = __float2bfloat16_rn(xs[j] - __bfloat162float(h[j]));
    }
    __nv_bfloat162 h0; h0.x = h[0]; h0.y = h[1];
    __nv_bfloat162 h1; h1.x = h[2]; h1.y = h[3];
    __nv_bfloat162 l0; l0.x = l[0]; l0.y = l[1];
    __nv_bfloat162 l1; l1.x = l[2]; l1.y = l[3];
    ((__nv_bfloat162*)hi)[i*2 + 0] = h0;
    ((__nv_bfloat162*)hi)[i*2 + 1] = h1;
    ((__nv_bfloat162*)lo)[i*2 + 0] = l0;
    ((__nv_bfloat162*)lo)[i*2 + 1] = l1;
}

// ======================= fp32 -> fp16 single convert =======================
__global__ __launch_bounds__(256)
void conv_fp16_kernel(const float* __restrict__ src, __half* __restrict__ dst, int n4)
{
    int i = blockIdx.x * blockDim.x + threadIdx.x;
    if (i >= n4) return;
    float4 x = ((const float4*)src)[i];
    __half2 a; a.x = __float2half_rn(x.x); a.y = __float2half_rn(x.y);
    __half2 b; b.x = __float2half_rn(x.z); b.y = __float2half_rn(x.w);
    ((__half2*)dst)[i*2 + 0] = a;
    ((__half2*)dst)[i*2 + 1] = b;
}

// ======================= mma.sync bf16x3 GEMM (NT) — QKV ===================
#define LDT   40
#define TILE_B (128*LDT*2)
#define STG_B  (4*TILE_B)
#define NSTG  3
#define GEMM_SMEM (NSTG*STG_B)

__device__ __forceinline__ void load_stage(
    uint32_t sbase, int stg,
    const __nv_bfloat16* __restrict__ Ah, const __nv_bfloat16* __restrict__ Al,
    const __nv_bfloat16* __restrict__ Bh, const __nv_bfloat16* __restrict__ Bl,
    int m0, int n0, int K, int k0, int tid)
{
    uint32_t sd = sbase + stg * STG_B;
#pragma unroll
    for (int i = 0; i < 8; i++) {
        int chunk = i * 256 + tid;
        int tile  = chunk >> 9;
        int idx   = chunk & 511;
        int row   = idx >> 2;
        int cseg  = idx & 3;
        const __nv_bfloat16* g = (tile == 0) ? Ah : (tile == 1) ? Al : (tile == 2) ? Bh : Bl;
        int grow = ((tile < 2) ? m0 : n0) + row;
        const char* src = (const char*)(g + (size_t)grow * K + k0) + cseg * 16;
        cpasync16(sd + tile * TILE_B + row * 80 + cseg * 16, src);
    }
}

__global__ __launch_bounds__(256, 1)
void gemm_mma(const __nv_bfloat16* __restrict__ Ah, const __nv_bfloat16* __restrict__ Al,
              const __nv_bfloat16* __restrict__ Bh, const __nv_bfloat16* __restrict__ Bl,
              float* __restrict__ C, int N, int K)
{
    extern __shared__ char dsm[];
    const uint32_t sb = smem_u32(dsm);
    const int tid = threadIdx.x;
    const int w = tid >> 5;
    const int l = tid & 31;
    const int wm = (w >> 2) * 64;
    const int wn = (w & 3) * 32;
    const int m0 = blockIdx.y * 128;
    const int n0 = blockIdx.x * 128;
    const int kiters = K / 32;

    load_stage(sb, 0, Ah, Al, Bh, Bl, m0, n0, K, 0, tid);  CP_COMMIT();
    load_stage(sb, 1, Ah, Al, Bh, Bl, m0, n0, K, 32, tid); CP_COMMIT();

    float acc[16][4];
#pragma unroll
    for (int i = 0; i < 16; i++)
#pragma unroll
        for (int j = 0; j < 4; j++) acc[i][j] = 0.f;

    const int a_row = (l & 15);
    const int a_kof = (l >> 4) * 8;
    const int b_row = (l & 7) + ((l >> 4) & 1) * 8;
    const int b_kof = ((l >> 3) & 1) * 8;

    for (int kt = 0; kt < kiters; kt++) {
        CP_WAIT1();
        __syncthreads();
        const uint32_t st = sb + (kt % 3) * STG_B;
        const uint32_t sAh = st;
        const uint32_t sAl = st + TILE_B;
        const uint32_t sBh = st + 2 * TILE_B;
        const uint32_t sBl = st + 3 * TILE_B;

#pragma unroll
        for (int ks = 0; ks < 2; ks++) {
            const int kbase = ks * 16;
            uint32_t ah[4][4], al[4][4], bh[2][4], bl[2][4];
#pragma unroll
            for (int mi = 0; mi < 4; mi++) {
                uint32_t off = (uint32_t)((wm + mi * 16 + a_row) * 80 + (kbase + a_kof) * 2);
                ldmx4(ah[mi], sAh + off);
                ldmx4(al[mi], sAl + off);
            }
#pragma unroll
            for (int ni2 = 0; ni2 < 2; ni2++) {
                uint32_t off = (uint32_t)((wn + ni2 * 16 + b_row) * 80 + (kbase + b_kof) * 2);
                ldmx4(bh[ni2], sBh + off);
                ldmx4(bl[ni2], sBl + off);
            }
#pragma unroll
            for (int mi = 0; mi < 4; mi++) {
#pragma unroll
                for (int ni = 0; ni < 4; ni++) {
                    const uint32_t* bhp = &bh[ni >> 1][(ni & 1) * 2];
                    const uint32_t* blp = &bl[ni >> 1][(ni & 1) * 2];
                    mma16816(acc[mi * 4 + ni], ah[mi], bhp);
                    mma16816(acc[mi * 4 + ni], al[mi], bhp);
                    mma16816(acc[mi * 4 + ni], ah[mi], blp);
                }
            }
        }
        __syncthreads();
        if (kt + 2 < kiters)
            load_stage(sb, (kt + 2) % 3, Ah, Al, Bh, Bl, m0, n0, K, (kt + 2) * 32, tid);
        CP_COMMIT();
    }

#pragma unroll
    for (int mi = 0; mi < 4; mi++) {
#pragma unroll
        for (int ni = 0; ni < 4; ni++) {
            int row = m0 + wm + mi * 16 + (l >> 2);
            int col = n0 + wn + ni * 8 + (l & 3) * 2;
            float* c = C + (size_t)row * N + col;
            float2 v0; v0.x = acc[mi * 4 + ni][0]; v0.y = acc[mi * 4 + ni][1];
            float2 v1; v1.x = acc[mi * 4 + ni][2]; v1.y = acc[mi * 4 + ni][3];
            *(float2*)c = v0;
            *(float2*)(c + 8 * (size_t)N) = v1;
        }
    }
}

// ======================= fp16 asym GEMM (A hi/lo x B single) — O-proj ======
#define STG_B3 (3*TILE_B)
#define GEMM_SMEM3 (NSTG*STG_B3)

__device__ __forceinline__ void load_stage3(
    uint32_t sbase, int stg,
    const __half* __restrict__ Ah, const __half* __restrict__ Al,
    const __half* __restrict__ Bs,
    int m0, int n0, int K, int k0, int tid)
{
    uint32_t sd = sbase + stg * STG_B3;
#pragma unroll
    for (int i = 0; i < 6; i++) {
        int chunk = i * 256 + tid;
        int tile  = chunk >> 9;         // 0..2
        int idx   = chunk & 511;
        int row   = idx >> 2;
        int cseg  = idx & 3;
        const __half* g = (tile == 0) ? Ah : (tile == 1) ? Al : Bs;
        int grow = ((tile < 2) ? m0 : n0) + row;
        const char* src = (const char*)(g + (size_t)grow * K + k0) + cseg * 16;
        cpasync16(sd + tile * TILE_B + row * 80 + cseg * 16, src);
    }
}

__global__ __launch_bounds__(256, 1)
void gemm_asym(const __half* __restrict__ Ah, const __half* __restrict__ Al,
               const __half* __restrict__ Bs,
               float* __restrict__ C, int N, int K)
{
    extern __shared__ char dsm[];
    const uint32_t sb = smem_u32(dsm);
    const int tid = threadIdx.x;
    const int w = tid >> 5;
    const int l = tid & 31;
    const int wm = (w >> 2) * 64;
    const int wn = (w & 3) * 32;
    const int m0 = blockIdx.y * 128;
    const int n0 = blockIdx.x * 128;
    const int kiters = K / 32;

    load_stage3(sb, 0, Ah, Al, Bs, m0, n0, K, 0, tid);  CP_COMMIT();
    load_stage3(sb, 1, Ah, Al, Bs, m0, n0, K, 32, tid); CP_COMMIT();

    float acc[16][4];
#pragma unroll
    for (int i = 0; i < 16; i++)
#pragma unroll
        for (int j = 0; j < 4; j++) acc[i][j] = 0.f;

    const int a_row = (l & 15);
    const int a_kof = (l >> 4) * 8;
    const int b_row = (l & 7) + ((l >> 4) & 1) * 8;
    const int b_kof = ((l >> 3) & 1) * 8;

    for (int kt = 0; kt < kiters; kt++) {
        CP_WAIT1();
        __syncthreads();
        const uint32_t st = sb + (kt % 3) * STG_B3;
        const uint32_t sAh = st;
        const uint32_t sAl = st + TILE_B;
        const uint32_t sBs = st + 2 * TILE_B;

#pragma unroll
        for (int ks = 0; ks < 2; ks++) {
            const int kbase = ks * 16;
            uint32_t ah[4][4], al[4][4], bh[2][4];
#pragma unroll
            for (int mi = 0; mi < 4; mi++) {
                uint32_t off = (uint32_t)((wm + mi * 16 + a_row) * 80 + (kbase + a_kof) * 2);
                ldmx4(ah[mi], sAh + off);
                ldmx4(al[mi], sAl + off);
            }
#pragma unroll
            for (int ni2 = 0; ni2 < 2; ni2++) {
                uint32_t off = (uint32_t)((wn + ni2 * 16 + b_row) * 80 + (kbase + b_kof) * 2);
                ldmx4(bh[ni2], sBs + off);
            }
#pragma unroll
            for (int mi = 0; mi < 4; mi++) {
#pragma unroll
                for (int ni = 0; ni < 4; ni++) {
                    const uint32_t* bhp = &bh[ni >> 1][(ni & 1) * 2];
                    mma16816h(acc[mi * 4 + ni], ah[mi], bhp);
                    mma16816h(acc[mi * 4 + ni], al[mi], bhp);
                }
            }
        }
        __syncthreads();
        if (kt + 2 < kiters)
            load_stage3(sb, (kt + 2) % 3, Ah, Al, Bs, m0, n0, K, (kt + 2) * 32, tid);
        CP_COMMIT();
    }

#pragma unroll
    for (int mi = 0; mi < 4; mi++) {
#pragma unroll
        for (int ni = 0; ni < 4; ni++) {
            int row = m0 + wm + mi * 16 + (l >> 2);
            int col = n0 + wn + ni * 8 + (l & 3) * 2;
            float* c = C + (size_t)row * N + col;
            float2 v0; v0.x = acc[mi * 4 + ni][0]; v0.y = acc[mi * 4 + ni][1];
            float2 v1; v1.x = acc[mi * 4 + ni][2]; v1.y = acc[mi * 4 + ni][3];
            *(float2*)c = v0;
            *(float2*)(c + 8 * (size_t)N) = v1;
        }
    }
}

// ---------------- RMSNorm + mrope -> fp16 operands --------------------------
__device__ __forceinline__ int mrope_axis(int d) {
    return d < 21 ? 0 : d < 42 ? 1 : d < 64 ? 2 : d < 85 ? 0 : d < 106 ? 1 : 2;
}

__global__ __launch_bounds__(256)
void norm_rope_kernel(const float* __restrict__ cosb, const float* __restrict__ sinb,
                      const float* __restrict__ qw,   const float* __restrict__ kw)
{
    const int m = blockIdx.x;
    const int b = m >> 11;
    const int s = m & (S_ - 1);
    const int warp = threadIdx.x >> 5;
    const int lane = threadIdx.x & 31;
    const float SC = 0.08838834764831845f;
    const float* tok = g_qkv + (size_t)m * NQKV;

#pragma unroll
    for (int it = 0; it < 4; it++) {
        int slot = warp + (it << 3);
        const float* src; const float* w; bool rope; float scale;
        __half *dh = nullptr, *dl = nullptr;   // dl == null -> single output
        if (slot < 16) {
            src = tok + slot * D_;
            size_t o = ((size_t)(b * H_ + slot) * S_ + s) * D_;
            dh = g_qh + o; dl = g_ql + o;
            w = qw; rope = true; scale = SC;
        } else if (slot < 24) {
            int hh = slot - 16;
            src = tok + 2048 + hh * D_;
            size_t o = ((size_t)(b * KV_ + hh) * S_ + s) * D_;
            dh = g_k16 + o;
            w = kw; rope = true; scale = 1.f;
        } else {
            int hh = slot - 24;
            src = tok + 3072 + hh * D_;
            size_t o = ((size_t)(b * KV_ + hh) * S_ + s) * D_;
            dh = g_v16 + o;
            w = nullptr; rope = false; scale = 1.f;
        }
        float4 x4 = *(const float4*)(src + lane * 4);
        float out[4] = {x4.x, x4.y, x4.z, x4.w};
        if (rope) {
            float x[4] = {out[0], out[1], out[2], out[3]};
            float ssum = x[0]*x[0] + x[1]*x[1] + x[2]*x[2] + x[3]*x[3];
#pragma unroll
            for (int o2 = 16; o2 > 0; o2 >>= 1)
                ssum += __shfl_xor_sync(0xffffffffu, ssum, o2);
            float r = rsqrtf(ssum * (1.0f / 128.0f) + 1e-6f);
            float4 w4 = *(const float4*)(w + lane * 4);
            float xn[4];
            xn[0] = x[0] * r * w4.x; xn[1] = x[1] * r * w4.y;
            xn[2] = x[2] * r * w4.z; xn[3] = x[3] * r * w4.w;
            float oth[4];
#pragma unroll
            for (int j = 0; j < 4; j++)
                oth[j] = __shfl_xor_sync(0xffffffffu, xn[j], 16);
            float sgn = (lane < 16) ? -1.f : 1.f;
            int dbase = lane * 4;
#pragma unroll
            for (int j = 0; j < 4; j++) {
                int d = dbase + j;
                int ax = mrope_axis(d);
                size_t ci = ((size_t)(ax * B_ + b) * S_ + s) * D_ + d;
                out[j] = (xn[j] * cosb[ci] + sgn * oth[j] * sinb[ci]) * scale;
            }
        }
        if (dl) {
            // hi/lo fp16
            __half h[4], lo[4];
#pragma unroll
            for (int j = 0; j < 4; j++) {
                h[j]  = __float2half_rn(out[j]);
                lo[j] = __float2half_rn(out[j] - __half2float(h[j]));
            }
            __half2* ph = (__half2*)(dh + lane * 4);
            __half2* pl = (__half2*)(dl + lane * 4);
            __half2 t;
            t.x = h[0];  t.y = h[1];  ph[0] = t;
            t.x = h[2];  t.y = h[3];  ph[1] = t;
            t.x = lo[0]; t.y = lo[1]; pl[0] = t;
            t.x = lo[2]; t.y = lo[3]; pl[1] = t;
        } else {
            // single fp16
            __half2* ph = (__half2*)(dh + lane * 4);
            __half2 t;
            t.x = __float2half_rn(out[0]); t.y = __float2half_rn(out[1]); ph[0] = t;
            t.x = __float2half_rn(out[2]); t.y = __float2half_rn(out[3]); ph[1] = t;
        }
    }
}

// ---------------- causal GQA flash attention (fp16, reduced mma) ------------
// CTA: 128 q rows, 256 threads. K-tile 64, double-buffered.
// QK: 2 mmas (Q hi/lo x K single). PV: 1 mma (P single x V single).
#define FSTR 136
#define QTILE_E (128*FSTR)
#define KTILE_E (64*FSTR)
#define FLASH_SMEM ((2*QTILE_E + 4*KTILE_E)*2)   // 139264 bytes
#define MASKV (-30000.0f)

__device__ __forceinline__ void load_kv_stage(
    __half* fsb, int st, int k0,
    const __half* Kp, const __half* Vp, int tid)
{
    __half* kd = fsb + 2*QTILE_E + st * 2 * KTILE_E;
    __half* vd = kd + KTILE_E;
#pragma unroll
    for (int i = 0; i < 4; i++) {
        int c = tid + i * 256;
        int r = c >> 4, cs = c & 15;
        size_t go = (size_t)(k0 + r) * D_ + cs * 8;
        uint32_t so = (uint32_t)(r * FSTR + cs * 8);
        cpasync16(smem_u32(kd + so), Kp + go);
        cpasync16(smem_u32(vd + so), Vp + go);
    }
}

__global__ __launch_bounds__(256, 1)
void flash_mma(__half* __restrict__ Oh, __half* __restrict__ Ol)
{
    extern __shared__ __half fsh[];
    __half* sQh = fsh;
    __half* sQl = fsh + QTILE_E;

    const int qt = (int)gridDim.x - 1 - (int)blockIdx.x;  // longest-first
    const int h = blockIdx.y, b = blockIdx.z;
    const int tid = threadIdx.x;
    const int w = tid >> 5;
    const int l = tid & 31;
    const int q0 = qt * 128;

    const __half* Qbh = g_qh + ((size_t)(b * H_ + h) * S_ + q0) * D_;
    const __half* Qbl = g_ql + ((size_t)(b * H_ + h) * S_ + q0) * D_;
    const __half* Kb  = g_k16 + (size_t)(b * KV_ + (h >> 1)) * S_ * D_;
    const __half* Vb  = g_v16 + (size_t)(b * KV_ + (h >> 1)) * S_ * D_;

    // prologue: Q hi/lo + KV(tile 0)
#pragma unroll
    for (int i = 0; i < 8; i++) {
        int c = tid + i * 256;
        int r = c >> 4, cs = c & 15;
        size_t go = (size_t)r * D_ + cs * 8;
        uint32_t so = (uint32_t)(r * FSTR + cs * 8);
        cpasync16(smem_u32(sQh + so), Qbh + go);
        cpasync16(smem_u32(sQl + so), Qbl + go);
    }
    load_kv_stage(fsh, 0, 0, Kb, Vb, tid);
    CP_COMMIT();

    float o[16][4];
#pragma unroll
    for (int i = 0; i < 16; i++)
#pragma unroll
        for (int j = 0; j < 4; j++) o[i][j] = 0.f;
    float mrow[2] = {MASKV, MASKV};
    float lrow[2] = {0.f, 0.f};

    const int r0 = l >> 2;
    const int a_row = (l & 15);
    const int a_kof = (l >> 4) * 8;
    const int b_row = (l & 7) + ((l >> 4) & 1) * 8;
    const int b_kof = ((l >> 3) & 1) * 8;
    const int v_row = (l & 15);
    const int v_cof = (l >> 4) * 8;
    const int wrow_lo = q0 + 16 * w;
    const int ntiles = 2 * qt + 2;

    for (int t = 0; t < ntiles; t++) {
        const int k0 = t * 64;
        const int st = t & 1;
        if (t + 1 < ntiles) {
            load_kv_stage(fsh, st ^ 1, (t + 1) * 64, Kb, Vb, tid);
            CP_COMMIT();
            CP_WAIT1();
        } else {
            CP_WAIT0();
        }
        __syncthreads();

        if (k0 <= wrow_lo + 15) {
            __half* sK = fsh + 2*QTILE_E + st * 2 * KTILE_E;
            __half* sV = sK + KTILE_E;

            // ---- S = Q K^T ----
            float s[8][4];
#pragma unroll
            for (int i = 0; i < 8; i++)
#pragma unroll
                for (int j = 0; j < 4; j++) s[i][j] = 0.f;

#pragma unroll
            for (int ks = 0; ks < 8; ks++) {
                uint32_t aoff = (uint32_t)((16 * w + a_row) * FSTR + ks * 16 + a_kof) * 2;
                uint32_t qh[4], ql[4];
                ldmx4(qh, smem_u32(sQh) + aoff);
                ldmx4(ql, smem_u32(sQl) + aoff);
#pragma unroll
                for (int ng = 0; ng < 4; ng++) {
                    uint32_t boff = (uint32_t)((16 * ng + b_row) * FSTR + ks * 16 + b_kof) * 2;
                    uint32_t kf[4];
                    ldmx4(kf, smem_u32(sK) + boff);
                    mma16816h(s[2*ng],   qh, &kf[0]);
                    mma16816h(s[2*ng],   ql, &kf[0]);
                    mma16816h(s[2*ng+1], qh, &kf[2]);
                    mma16816h(s[2*ng+1], ql, &kf[2]);
                }
            }

            // ---- causal mask (boundary k-tiles only) ----
            if (k0 + 63 > wrow_lo) {
                int grow0 = wrow_lo + r0;
                int grow1 = grow0 + 8;
#pragma unroll
                for (int nt = 0; nt < 8; nt++) {
                    int col = k0 + nt * 8 + (l & 3) * 2;
                    if (col > grow0)     s[nt][0] = MASKV;
                    if (col + 1 > grow0) s[nt][1] = MASKV;
                    if (col > grow1)     s[nt][2] = MASKV;
                    if (col + 1 > grow1) s[nt][3] = MASKV;
                }
            }

            // ---- online softmax ----
            float rm0 = MASKV, rm1 = MASKV;
#pragma unroll
            for (int nt = 0; nt < 8; nt++) {
                rm0 = fmaxf(rm0, fmaxf(s[nt][0], s[nt][1]));
                rm1 = fmaxf(rm1, fmaxf(s[nt][2], s[nt][3]));
            }
            rm0 = fmaxf(rm0, __shfl_xor_sync(0xffffffffu, rm0, 1));
            rm0 = fmaxf(rm0, __shfl_xor_sync(0xffffffffu, rm0, 2));
            rm1 = fmaxf(rm1, __shfl_xor_sync(0xffffffffu, rm1, 1));
            rm1 = fmaxf(rm1, __shfl_xor_sync(0xffffffffu, rm1, 2));

            float mn0 = fmaxf(mrow[0], rm0);
            float mn1 = fmaxf(mrow[1], rm1);
            float alpha0 = fexp(mrow[0] - mn0);
            float alpha1 = fexp(mrow[1] - mn1);
            mrow[0] = mn0; mrow[1] = mn1;

            float rs0 = 0.f, rs1 = 0.f;
#pragma unroll
            for (int nt = 0; nt < 8; nt++) {
                s[nt][0] = fexp(s[nt][0] - mn0);
                s[nt][1] = fexp(s[nt][1] - mn0);
                s[nt][2] = fexp(s[nt][2] - mn1);
                s[nt][3] = fexp(s[nt][3] - mn1);
                rs0 += s[nt][0] + s[nt][1];
                rs1 += s[nt][2] + s[nt][3];
            }
            rs0 += __shfl_xor_sync(0xffffffffu, rs0, 1);
            rs0 += __shfl_xor_sync(0xffffffffu, rs0, 2);
            rs1 += __shfl_xor_sync(0xffffffffu, rs1, 1);
            rs1 += __shfl_xor_sync(0xffffffffu, rs1, 2);
            lrow[0] = lrow[0] * alpha0 + rs0;
            lrow[1] = lrow[1] * alpha1 + rs1;

#pragma unroll
            for (int nt = 0; nt < 16; nt++) {
                o[nt][0] *= alpha0; o[nt][1] *= alpha0;
                o[nt][2] *= alpha1; o[nt][3] *= alpha1;
            }

            // ---- O += P V : P single fp16 in regs (C-frag -> A-frag perm) ----
#pragma unroll
            for (int ks = 0; ks < 4; ks++) {
                uint32_t pa[4];
                pa[0] = packh(s[2*ks][0],   s[2*ks][1]);
                pa[1] = packh(s[2*ks][2],   s[2*ks][3]);
                pa[2] = packh(s[2*ks+1][0], s[2*ks+1][1]);
                pa[3] = packh(s[2*ks+1][2], s[2*ks+1][3]);
#pragma unroll
                for (int dg = 0; dg < 8; dg++) {
                    uint32_t voff = (uint32_t)((ks * 16 + v_row) * FSTR + dg * 16 + v_cof) * 2;
                    uint32_t vf[4];
                    ldmx4t(vf, smem_u32(sV) + voff);
                    mma16816h(o[2*dg],   pa, &vf[0]);
                    mma16816h(o[2*dg+1], pa, &vf[2]);
                }
            }
        }
        __syncthreads();
    }

    // ---- epilogue: normalize, fp16 hi/lo out ----
    float inv0 = 1.f / lrow[0];
    float inv1 = 1.f / lrow[1];
    size_t row0 = (size_t)b * S_ + q0 + 16 * w + r0;
    size_t row1 = row0 + 8;
    int colb = h * D_ + (l & 3) * 2;
#pragma unroll
    for (int nt = 0; nt < 16; nt++) {
        int col = colb + nt * 8;
        float v0 = o[nt][0] * inv0, v1 = o[nt][1] * inv0;
        float v2 = o[nt][2] * inv1, v3 = o[nt][3] * inv1;
        uint32_t h0 = packh(v0, v1);
        __half2 th = *(__half2*)&h0;
        uint32_t lo0 = packh(v0 - __half2float(th.x), v1 - __half2float(th.y));
        *(uint32_t*)(Oh + row0 * (H_*D_) + col) = h0;
        *(uint32_t*)(Ol + row0 * (H_*D_) + col) = lo0;
        uint32_t h1 = packh(v2, v3);
        __half2 th1 = *(__half2*)&h1;
        uint32_t lo1 = packh(v2 - __half2float(th1.x), v3 - __half2float(th1.y));
        *(uint32_t*)(Oh + row1 * (H_*D_) + col) = h1;
        *(uint32_t*)(Ol + row1 * (H_*D_) + col) = lo1;
    }
}

// ---------------- launcher ---------------------------------------------------
static void launch_split(const float* src, __nv_bfloat16* hi, __nv_bfloat16* lo, int n)
{
    int n4 = n / 4;
    split_bf16_kernel<<<(n4 + 255) / 256, 256>>>(src, hi, lo, n4);
}

extern "C" void kernel_launch(void* const* d_in, const int* in_sizes, int n_in,
                              void* d_out, int out_size)
{
    const float* hidden   = (const float*)d_in[0];
    const float* cosb     = (const float*)d_in[1];
    const float* sinb     = (const float*)d_in[2];
    const float* q_w      = (const float*)d_in[3];
    const float* k_w      = (const float*)d_in[4];
    const float* v_w      = (const float*)d_in[5];
    const float* o_w      = (const float*)d_in[6];
    const float* q_norm_w = (const float*)d_in[7];
    const float* k_norm_w = (const float*)d_in[8];
    float* out = (float*)d_out;

    float* pqkv;
    cudaGetSymbolAddress((void**)&pqkv, g_qkv);

    __nv_bfloat16 *hidh, *hidl, *wh, *wl;
    __half *ow16, *ath, *atl;
    cudaGetSymbolAddress((void**)&hidh, g_hid_h); cudaGetSymbolAddress((void**)&hidl, g_hid_l);
    cudaGetSymbolAddress((void**)&wh,   g_w_h);   cudaGetSymbolAddress((void**)&wl,   g_w_l);
    cudaGetSymbolAddress((void**)&ow16, g_ow16);
    cudaGetSymbolAddress((void**)&ath,  g_at_h);  cudaGetSymbolAddress((void**)&atl,  g_at_l);

    cudaFuncSetAttribute(gemm_mma,  cudaFuncAttributeMaxDynamicSharedMemorySize, GEMM_SMEM);
    cudaFuncSetAttribute(gemm_asym, cudaFuncAttributeMaxDynamicSharedMemorySize, GEMM_SMEM3);
    cudaFuncSetAttribute(flash_mma, cudaFuncAttributeMaxDynamicSharedMemorySize, FLASH_SMEM);

    // 1) splits/converts
    launch_split(hidden, hidh, hidl, MTOK * HID_);
    launch_split(q_w, wh,                 wl,                 H_*D_*HID_);
    launch_split(k_w, wh + (size_t)2048*HID_, wl + (size_t)2048*HID_, KV_*D_*HID_);
    launch_split(v_w, wh + (size_t)3072*HID_, wl + (size_t)3072*HID_, KV_*D_*HID_);
    conv_fp16_kernel<<<(HID_*H_*D_/4 + 255)/256, 256>>>(o_w, ow16, HID_*H_*D_/4);

    // 2) fused QKV projection (bf16x3, full accuracy)
    gemm_mma<<<dim3(NQKV/128, MTOK/128), 256, GEMM_SMEM>>>(hidh, hidl, wh, wl, pqkv, NQKV, HID_);

    // 3) RMSNorm + mrope -> fp16 operands (Q hi/lo, K single, V single)
    norm_rope_kernel<<<MTOK, 256>>>(cosb, sinb, q_norm_w, k_norm_w);

    // 4) flash attention: QK 2-mma, PV 1-mma
    flash_mma<<<dim3(S_ / 128, H_, B_), 256, FLASH_SMEM>>>(ath, atl);

    // 5) O-projection (fp16 asym: A hi/lo x B single, 2-mma) -> d_out
    gemm_asym<<<dim3(HID_/128, MTOK/128), 256, GEMM_SMEM3>>>(ath, atl, ow16, out, HID_, H_*D_);
}